// round 1
// baseline (speedup 1.0000x reference)
#include <cuda_runtime.h>
#include <math.h>

// Problem constants
#define Bn  4
#define Sn  2048
#define En  1024
#define Hn  16
#define DKn 64
#define Mn  (Bn * Sn)     // 8192 rows for projections

// ---------------- scratch (device globals; no allocation allowed) ----------
__device__ float g_Q[Bn * Hn * Sn * DKn];   // (B,H,S,DK)
__device__ float g_K[Bn * Hn * Sn * DKn];
__device__ float g_V[Bn * Hn * Sn * DKn];
__device__ float g_ctx[Mn * En];            // (B*S, E) row-major

// ---------------- SGEMM config ----------------
#define BM 128
#define BN 128
#define BK 16
#define SA 132   // padded smem row stride (floats), multiple of 4 for float4

// Y = X @ W^T : X (M,K) row-major, W (N,K) row-major; each block computes
// a 128x128 tile, 256 threads, 8x8 per thread.
// mode: write head-split QKV (blockIdx.z selects W / out).
__global__ __launch_bounds__(256)
void gemm_qkv_kernel(const float* __restrict__ X,
                     const float* __restrict__ Wq,
                     const float* __restrict__ Wk,
                     const float* __restrict__ Wv)
{
    const int z = blockIdx.z;
    const float* __restrict__ W = (z == 0) ? Wq : (z == 1) ? Wk : Wv;
    float* __restrict__ out = (z == 0) ? g_Q : (z == 1) ? g_K : g_V;

    __shared__ float As[BK * SA];
    __shared__ float Bs[BK * SA];

    const int tid = threadIdx.x;
    const int tx = tid & 15;          // 0..15 -> output cols
    const int ty = tid >> 4;          // 0..15 -> output rows
    const int rowBase = blockIdx.y * BM;
    const int colBase = blockIdx.x * BN;

    const int lrow = tid >> 2;        // 0..63
    const int lc4  = (tid & 3) * 4;   // 0,4,8,12

    float acc[8][8];
#pragma unroll
    for (int i = 0; i < 8; i++)
#pragma unroll
        for (int j = 0; j < 8; j++) acc[i][j] = 0.f;

    for (int k0 = 0; k0 < En; k0 += BK) {
#pragma unroll
        for (int rr = 0; rr < 2; rr++) {
            int r = lrow + rr * 64;
            float4 va = *(const float4*)&X[(rowBase + r) * En + k0 + lc4];
            As[(lc4 + 0) * SA + r] = va.x;
            As[(lc4 + 1) * SA + r] = va.y;
            As[(lc4 + 2) * SA + r] = va.z;
            As[(lc4 + 3) * SA + r] = va.w;
            float4 vb = *(const float4*)&W[(colBase + r) * En + k0 + lc4];
            Bs[(lc4 + 0) * SA + r] = vb.x;
            Bs[(lc4 + 1) * SA + r] = vb.y;
            Bs[(lc4 + 2) * SA + r] = vb.z;
            Bs[(lc4 + 3) * SA + r] = vb.w;
        }
        __syncthreads();

#pragma unroll
        for (int kk = 0; kk < BK; kk++) {
            float a[8], b[8];
            float4 a0 = *(const float4*)&As[kk * SA + ty * 8];
            float4 a1 = *(const float4*)&As[kk * SA + ty * 8 + 4];
            float4 b0 = *(const float4*)&Bs[kk * SA + tx * 8];
            float4 b1 = *(const float4*)&Bs[kk * SA + tx * 8 + 4];
            a[0]=a0.x;a[1]=a0.y;a[2]=a0.z;a[3]=a0.w;a[4]=a1.x;a[5]=a1.y;a[6]=a1.z;a[7]=a1.w;
            b[0]=b0.x;b[1]=b0.y;b[2]=b0.z;b[3]=b0.w;b[4]=b1.x;b[5]=b1.y;b[6]=b1.z;b[7]=b1.w;
#pragma unroll
            for (int i = 0; i < 8; i++)
#pragma unroll
                for (int j = 0; j < 8; j++)
                    acc[i][j] = fmaf(a[i], b[j], acc[i][j]);
        }
        __syncthreads();
    }

    // scatter-store in head-split layout (B,H,S,DK)
#pragma unroll
    for (int i = 0; i < 8; i++) {
        int m = rowBase + ty * 8 + i;          // = b*S + s
        int b = m >> 11;                        // /2048
        int s = m & (Sn - 1);
#pragma unroll
        for (int j = 0; j < 8; j++) {
            int n = colBase + tx * 8 + j;       // = h*64 + d
            int h = n >> 6;
            int d = n & 63;
            out[((b * Hn + h) * Sn + s) * DKn + d] = acc[i][j];
        }
    }
}

// out = ctx @ Wo^T, row-major output
__global__ __launch_bounds__(256)
void gemm_out_kernel(const float* __restrict__ Wo, float* __restrict__ out)
{
    __shared__ float As[BK * SA];
    __shared__ float Bs[BK * SA];

    const int tid = threadIdx.x;
    const int tx = tid & 15;
    const int ty = tid >> 4;
    const int rowBase = blockIdx.y * BM;
    const int colBase = blockIdx.x * BN;
    const int lrow = tid >> 2;
    const int lc4  = (tid & 3) * 4;

    float acc[8][8];
#pragma unroll
    for (int i = 0; i < 8; i++)
#pragma unroll
        for (int j = 0; j < 8; j++) acc[i][j] = 0.f;

    for (int k0 = 0; k0 < En; k0 += BK) {
#pragma unroll
        for (int rr = 0; rr < 2; rr++) {
            int r = lrow + rr * 64;
            float4 va = *(const float4*)&g_ctx[(rowBase + r) * En + k0 + lc4];
            As[(lc4 + 0) * SA + r] = va.x;
            As[(lc4 + 1) * SA + r] = va.y;
            As[(lc4 + 2) * SA + r] = va.z;
            As[(lc4 + 3) * SA + r] = va.w;
            float4 vb = *(const float4*)&Wo[(colBase + r) * En + k0 + lc4];
            Bs[(lc4 + 0) * SA + r] = vb.x;
            Bs[(lc4 + 1) * SA + r] = vb.y;
            Bs[(lc4 + 2) * SA + r] = vb.z;
            Bs[(lc4 + 3) * SA + r] = vb.w;
        }
        __syncthreads();

#pragma unroll
        for (int kk = 0; kk < BK; kk++) {
            float a[8], b[8];
            float4 a0 = *(const float4*)&As[kk * SA + ty * 8];
            float4 a1 = *(const float4*)&As[kk * SA + ty * 8 + 4];
            float4 b0 = *(const float4*)&Bs[kk * SA + tx * 8];
            float4 b1 = *(const float4*)&Bs[kk * SA + tx * 8 + 4];
            a[0]=a0.x;a[1]=a0.y;a[2]=a0.z;a[3]=a0.w;a[4]=a1.x;a[5]=a1.y;a[6]=a1.z;a[7]=a1.w;
            b[0]=b0.x;b[1]=b0.y;b[2]=b0.z;b[3]=b0.w;b[4]=b1.x;b[5]=b1.y;b[6]=b1.z;b[7]=b1.w;
#pragma unroll
            for (int i = 0; i < 8; i++)
#pragma unroll
                for (int j = 0; j < 8; j++)
                    acc[i][j] = fmaf(a[i], b[j], acc[i][j]);
        }
        __syncthreads();
    }

#pragma unroll
    for (int i = 0; i < 8; i++) {
        int m = rowBase + ty * 8 + i;
        float4 v0, v1;
        v0.x = acc[i][0]; v0.y = acc[i][1]; v0.z = acc[i][2]; v0.w = acc[i][3];
        v1.x = acc[i][4]; v1.y = acc[i][5]; v1.z = acc[i][6]; v1.w = acc[i][7];
        *(float4*)&out[m * En + colBase + tx * 8]     = v0;
        *(float4*)&out[m * En + colBase + tx * 8 + 4] = v1;
    }
}

// ---------------- flash attention (fp32, online softmax) ----------------
// grid: (S/64, B*H), block 256. Each block: 64 queries x full K loop.
#define QT 64
#define KT 64
#define SQ 68   // padded stride for Qs/Ks/Ps
#define SMEM_ATTN ((3 * QT * SQ + KT * DKn) * 4)

__global__ __launch_bounds__(256)
void attn_kernel()
{
    extern __shared__ float sm[];
    float* Qs = sm;                       // 64 x 68
    float* Ks = Qs + QT * SQ;             // 64 x 68
    float* Ps = Ks + QT * SQ;             // 64 x 68
    float* Vs = Ps + QT * SQ;             // 64 x 64

    const int tid = threadIdx.x;
    const int tx = tid & 15;     // cols group
    const int ty = tid >> 4;     // rows group
    const int q0 = blockIdx.x * QT;
    const int bh = blockIdx.y;          // b*H + h
    const int b  = bh / Hn;
    const int h  = bh % Hn;

    const float* __restrict__ Qg = g_Q + (bh * Sn) * DKn;
    const float* __restrict__ Kg = g_K + (bh * Sn) * DKn;
    const float* __restrict__ Vg = g_V + (bh * Sn) * DKn;

    // load Q tile, pre-scaled by 1/sqrt(64)
    {
        int r = tid >> 4;         // 0..15
        int f = (tid & 15) * 4;   // float4 col
#pragma unroll
        for (int rr = 0; rr < 4; rr++) {
            int row = r + rr * 16;
            float4 v = *(const float4*)&Qg[(q0 + row) * DKn + f];
            Qs[row * SQ + f + 0] = v.x * 0.125f;
            Qs[row * SQ + f + 1] = v.y * 0.125f;
            Qs[row * SQ + f + 2] = v.z * 0.125f;
            Qs[row * SQ + f + 3] = v.w * 0.125f;
        }
    }

    float acc[4][4];
    float mrow[4], lrow[4];
#pragma unroll
    for (int i = 0; i < 4; i++) {
        mrow[i] = -INFINITY; lrow[i] = 0.f;
#pragma unroll
        for (int j = 0; j < 4; j++) acc[i][j] = 0.f;
    }

    for (int kv0 = 0; kv0 < Sn; kv0 += KT) {
        // load K,V tiles
        {
            int r = tid >> 4;
            int f = (tid & 15) * 4;
#pragma unroll
            for (int rr = 0; rr < 4; rr++) {
                int row = r + rr * 16;
                float4 kvv = *(const float4*)&Kg[(kv0 + row) * DKn + f];
                Ks[row * SQ + f + 0] = kvv.x;
                Ks[row * SQ + f + 1] = kvv.y;
                Ks[row * SQ + f + 2] = kvv.z;
                Ks[row * SQ + f + 3] = kvv.w;
                float4 vvv = *(const float4*)&Vg[(kv0 + row) * DKn + f];
                *(float4*)&Vs[row * DKn + f] = vvv;
            }
        }
        __syncthreads();

        // S = Q K^T
        float s[4][4];
#pragma unroll
        for (int i = 0; i < 4; i++)
#pragma unroll
            for (int j = 0; j < 4; j++) s[i][j] = 0.f;

#pragma unroll 16
        for (int k = 0; k < DKn; k++) {
            float qv[4], kv[4];
#pragma unroll
            for (int i = 0; i < 4; i++) qv[i] = Qs[(ty * 4 + i) * SQ + k];
#pragma unroll
            for (int j = 0; j < 4; j++) kv[j] = Ks[(tx * 4 + j) * SQ + k];
#pragma unroll
            for (int i = 0; i < 4; i++)
#pragma unroll
                for (int j = 0; j < 4; j++)
                    s[i][j] = fmaf(qv[i], kv[j], s[i][j]);
        }

        // online softmax per row (reduce across tx = lane bits 0..3)
#pragma unroll
        for (int i = 0; i < 4; i++) {
            float mx = s[i][0];
#pragma unroll
            for (int j = 1; j < 4; j++) mx = fmaxf(mx, s[i][j]);
#pragma unroll
            for (int off = 1; off < 16; off <<= 1)
                mx = fmaxf(mx, __shfl_xor_sync(0xffffffffu, mx, off));
            float mnew = fmaxf(mrow[i], mx);
            float alpha = __expf(mrow[i] - mnew);
            float rs = 0.f;
#pragma unroll
            for (int j = 0; j < 4; j++) {
                s[i][j] = __expf(s[i][j] - mnew);
                rs += s[i][j];
            }
#pragma unroll
            for (int off = 1; off < 16; off <<= 1)
                rs += __shfl_xor_sync(0xffffffffu, rs, off);
            lrow[i] = lrow[i] * alpha + rs;
            mrow[i] = mnew;
#pragma unroll
            for (int j = 0; j < 4; j++) acc[i][j] *= alpha;
        }

        // store P
#pragma unroll
        for (int i = 0; i < 4; i++)
#pragma unroll
            for (int j = 0; j < 4; j++)
                Ps[(ty * 4 + i) * SQ + tx * 4 + j] = s[i][j];
        __syncthreads();

        // O += P @ V
#pragma unroll 16
        for (int k = 0; k < KT; k++) {
            float pv[4], vv[4];
#pragma unroll
            for (int i = 0; i < 4; i++) pv[i] = Ps[(ty * 4 + i) * SQ + k];
#pragma unroll
            for (int j = 0; j < 4; j++) vv[j] = Vs[k * DKn + tx * 4 + j];
#pragma unroll
            for (int i = 0; i < 4; i++)
#pragma unroll
                for (int j = 0; j < 4; j++)
                    acc[i][j] = fmaf(pv[i], vv[j], acc[i][j]);
        }
        __syncthreads();
    }

    // normalize + write ctx in (B,S,E) layout
#pragma unroll
    for (int i = 0; i < 4; i++) {
        float rinv = 1.f / lrow[i];
        int srow = q0 + ty * 4 + i;
        float4 v;
        v.x = acc[i][0] * rinv;
        v.y = acc[i][1] * rinv;
        v.z = acc[i][2] * rinv;
        v.w = acc[i][3] * rinv;
        *(float4*)&g_ctx[(b * Sn + srow) * En + h * DKn + tx * 4] = v;
    }
}

// ---------------- launch ----------------
extern "C" void kernel_launch(void* const* d_in, const int* in_sizes, int n_in,
                              void* d_out, int out_size)
{
    (void)in_sizes; (void)n_in; (void)out_size;
    const float* x  = (const float*)d_in[0];
    const float* Wq = (const float*)d_in[1];
    const float* Wk = (const float*)d_in[2];
    const float* Wv = (const float*)d_in[3];
    const float* Wo = (const float*)d_in[4];
    float* out = (float*)d_out;

    // QKV projections (z = 0,1,2)
    dim3 gq(En / BN, Mn / BM, 3);
    gemm_qkv_kernel<<<gq, 256>>>(x, Wq, Wk, Wv);

    // flash attention
    cudaFuncSetAttribute(attn_kernel,
                         cudaFuncAttributeMaxDynamicSharedMemorySize, SMEM_ATTN);
    dim3 ga(Sn / QT, Bn * Hn);
    attn_kernel<<<ga, 256, SMEM_ATTN>>>();

    // output projection
    dim3 go(En / BN, Mn / BM);
    gemm_out_kernel<<<go, 256>>>(Wo, out);
}

// round 4
// speedup vs baseline: 3.1479x; 3.1479x over previous
#include <cuda_runtime.h>
#include <cuda_bf16.h>
#include <cstdint>
#include <math.h>

#define Bn  4
#define Sn  2048
#define En  1024
#define Hn  16
#define DKn 64
#define Mn  (Bn * Sn)   // 8192

// ==================== device global scratch ====================
__device__ __nv_bfloat16 g_Xh[Mn * En], g_Xl[Mn * En];
__device__ __nv_bfloat16 g_Wh[4 * En * En], g_Wl[4 * En * En];
__device__ __nv_bfloat16 g_Qh[Mn * En], g_Ql[Mn * En];   // (B,H,S,DK)
__device__ __nv_bfloat16 g_Kh[Mn * En], g_Kl[Mn * En];   // (B,H,S,DK)
__device__ __nv_bfloat16 g_Vh[Mn * En], g_Vl[Mn * En];   // (B,H,DK,S) d-major
__device__ __nv_bfloat16 g_Ch[Mn * En], g_Cl[Mn * En];   // ctx (B,S,E)

// ==================== helpers ====================
__device__ __forceinline__ uint32_t smem_to_u32(const void* p) {
    uint32_t a;
    asm("{ .reg .u64 t; cvta.to.shared.u64 t, %1; cvt.u32.u64 %0, t; }"
        : "=r"(a) : "l"(p));
    return a;
}
__device__ __forceinline__ void ldsm4(uint32_t addr, uint32_t r[4]) {
    asm volatile("ldmatrix.sync.aligned.m8n8.x4.shared.b16 {%0,%1,%2,%3}, [%4];"
                 : "=r"(r[0]), "=r"(r[1]), "=r"(r[2]), "=r"(r[3]) : "r"(addr));
}
__device__ __forceinline__ void mma16816(float d[4], const uint32_t a[4],
                                         uint32_t b0, uint32_t b1) {
    asm volatile(
        "mma.sync.aligned.m16n8k16.row.col.f32.bf16.bf16.f32 "
        "{%0,%1,%2,%3}, {%4,%5,%6,%7}, {%8,%9}, {%0,%1,%2,%3};"
        : "+f"(d[0]), "+f"(d[1]), "+f"(d[2]), "+f"(d[3])
        : "r"(a[0]), "r"(a[1]), "r"(a[2]), "r"(a[3]), "r"(b0), "r"(b1));
}
#define CP16(saddr, gptr) \
    asm volatile("cp.async.cg.shared.global [%0], [%1], 16;" \
                 :: "r"(saddr), "l"(gptr))
#define CP_COMMIT() asm volatile("cp.async.commit_group;")
#define CP_WAIT0()  asm volatile("cp.async.wait_group 0;")
#define CP_WAIT1()  asm volatile("cp.async.wait_group 1;")

// pack two f32 into bf16x2 (lo = a, hi = b)
__device__ __forceinline__ uint32_t pack_bf16x2(float a, float b) {
    uint32_t r;
    asm("cvt.rn.bf16x2.f32 %0, %1, %2;" : "=r"(r) : "f"(b), "f"(a));
    return r;
}
// hi/lo split of a f32 pair into two bf16x2 regs
__device__ __forceinline__ void packsplit(float a, float b, uint32_t& h, uint32_t& l) {
    h = pack_bf16x2(a, b);
    float ha = __uint_as_float(h << 16);
    float hb = __uint_as_float(h & 0xffff0000u);
    l = pack_bf16x2(a - ha, b - hb);
}
__device__ __forceinline__ void split2(float v, __nv_bfloat16& h, __nv_bfloat16& l) {
    h = __float2bfloat16_rn(v);
    l = __float2bfloat16_rn(v - __bfloat162float(h));
}

// ==================== split fp32 -> bf16 hi/lo ====================
// sel 0: x -> g_Xh/g_Xl ; sel 1..4: W -> g_Wh/g_Wl slice (sel-1)
__global__ __launch_bounds__(256)
void split_kernel(const float* __restrict__ src, int sel, int n4)
{
    int i = blockIdx.x * blockDim.x + threadIdx.x;
    if (i >= n4) return;
    __nv_bfloat16 *hi, *lo;
    if (sel == 0) { hi = g_Xh; lo = g_Xl; }
    else { hi = g_Wh + (size_t)(sel - 1) * En * En;
           lo = g_Wl + (size_t)(sel - 1) * En * En; }
    float4 v = ((const float4*)src)[i];
    __nv_bfloat16 h0, h1, h2, h3, l0, l1, l2, l3;
    split2(v.x, h0, l0); split2(v.y, h1, l1);
    split2(v.z, h2, l2); split2(v.w, h3, l3);
    ((__nv_bfloat162*)hi)[i * 2 + 0] = __nv_bfloat162(h0, h1);
    ((__nv_bfloat162*)hi)[i * 2 + 1] = __nv_bfloat162(h2, h3);
    ((__nv_bfloat162*)lo)[i * 2 + 0] = __nv_bfloat162(l0, l1);
    ((__nv_bfloat162*)lo)[i * 2 + 1] = __nv_bfloat162(l2, l3);
}

// ==================== MMA GEMM: Y = A @ W^T ====================
// 128x128 CTA tile, 8 warps (wm 0..1 x wn 0..3), warp 64x32, BK=32,
// cp.async double buffer. mode 0: z picks Q/K/V epilogue; mode 1: fp32 out.
#define GSB  80               // smem row stride bytes (32 bf16 + pad)
#define GT   (128 * GSB)      // 10240 B per tile
#define GEMM_SMEM (8 * GT)    // 81920 B

#define GEMM_ISSUE(buf, k0) do {                                            \
    const __nv_bfloat16* _s[4] = { pA0, pA1, pB0, pB1 };                    \
    _Pragma("unroll")                                                       \
    for (int _t = 0; _t < 4; _t++) {                                        \
        uint32_t _db = sb + ((buf) * 4 + _t) * GT;                          \
        _Pragma("unroll")                                                   \
        for (int _i = 0; _i < 2; _i++) {                                    \
            int _u = _i * 256 + tid; int _r = _u >> 2; int _c = _u & 3;     \
            const void* _g = _s[_t] + (size_t)_r * En + (k0) + _c * 8;      \
            CP16(_db + _r * GSB + _c * 16, _g);                             \
        }                                                                   \
    }                                                                       \
    CP_COMMIT();                                                            \
} while (0)

__global__ __launch_bounds__(256, 1)
void gemm_mma_kernel(int mode, float* __restrict__ outp)
{
    extern __shared__ char sm[];
    const uint32_t sb = smem_to_u32(sm);
    const int tid = threadIdx.x, wid = tid >> 5, lane = tid & 31;
    const int wm = wid >> 2, wn = wid & 3;
    const int z = blockIdx.z;
    const int ws = (mode == 1) ? 3 : z;
    const int rowBase = blockIdx.y * 128, colBase = blockIdx.x * 128;

    const __nv_bfloat16* __restrict__ pA0 =
        (mode == 0 ? g_Xh : g_Ch) + (size_t)rowBase * En;
    const __nv_bfloat16* __restrict__ pA1 =
        (mode == 0 ? g_Xl : g_Cl) + (size_t)rowBase * En;
    const __nv_bfloat16* __restrict__ pB0 =
        g_Wh + (size_t)ws * En * En + (size_t)colBase * En;
    const __nv_bfloat16* __restrict__ pB1 =
        g_Wl + (size_t)ws * En * En + (size_t)colBase * En;

    float acc[4][4][4];
#pragma unroll
    for (int a = 0; a < 4; a++)
#pragma unroll
        for (int b = 0; b < 4; b++)
#pragma unroll
            for (int c = 0; c < 4; c++) acc[a][b][c] = 0.f;

    const int rin = lane & 15;
    const int chf = lane >> 4;

    GEMM_ISSUE(0, 0);
#pragma unroll 1
    for (int ch = 0; ch < 32; ch++) {
        const int buf = ch & 1;
        if (ch < 31) { GEMM_ISSUE(buf ^ 1, (ch + 1) * 32); CP_WAIT1(); }
        else         { CP_WAIT0(); }
        __syncthreads();
        const uint32_t aH = sb + (buf * 4 + 0) * GT;
        const uint32_t aL = sb + (buf * 4 + 1) * GT;
        const uint32_t bH = sb + (buf * 4 + 2) * GT;
        const uint32_t bL = sb + (buf * 4 + 3) * GT;

        uint32_t bf[2][2][2][4];   // [hl][ks][p][4]
#pragma unroll
        for (int ks = 0; ks < 2; ks++)
#pragma unroll
            for (int p = 0; p < 2; p++) {
                uint32_t off = (uint32_t)((wn * 32 + p * 16 + rin) * GSB
                                          + (ks * 16 + chf * 8) * 2);
                ldsm4(bH + off, bf[0][ks][p]);
                ldsm4(bL + off, bf[1][ks][p]);
            }
#pragma unroll
        for (int mt = 0; mt < 4; mt++)
#pragma unroll
            for (int ks = 0; ks < 2; ks++) {
                uint32_t ah_[4], al_[4];
                uint32_t off = (uint32_t)((wm * 64 + mt * 16 + rin) * GSB
                                          + (ks * 16 + chf * 8) * 2);
                ldsm4(aH + off, ah_);
                ldsm4(aL + off, al_);
#pragma unroll
                for (int nt = 0; nt < 4; nt++) {
                    const int p = nt >> 1, e = nt & 1;
                    mma16816(acc[mt][nt], ah_, bf[0][ks][p][e], bf[0][ks][p][2 + e]);
                    mma16816(acc[mt][nt], ah_, bf[1][ks][p][e], bf[1][ks][p][2 + e]);
                    mma16816(acc[mt][nt], al_, bf[0][ks][p][e], bf[0][ks][p][2 + e]);
                }
            }
        __syncthreads();
    }

    // epilogue
    const int qr = lane >> 2, qc = (lane & 3) * 2;
#pragma unroll
    for (int mt = 0; mt < 4; mt++)
#pragma unroll
        for (int hf = 0; hf < 2; hf++) {
            const int m = rowBase + wm * 64 + mt * 16 + qr + hf * 8;
#pragma unroll
            for (int nt = 0; nt < 4; nt++) {
                const int n = colBase + wn * 32 + nt * 8 + qc;
                const float v0 = acc[mt][nt][hf * 2 + 0];
                const float v1 = acc[mt][nt][hf * 2 + 1];
                if (mode == 1) {
                    float2 o; o.x = v0; o.y = v1;
                    *(float2*)&outp[(size_t)m * En + n] = o;
                } else {
                    const int b = m >> 11, s = m & (Sn - 1);
                    const int h = n >> 6,  d = n & 63;
                    __nv_bfloat16 h0, h1, l0, l1;
                    split2(v0, h0, l0); split2(v1, h1, l1);
                    if (z == 2) {   // V: d-major (B,H,DK,S)
                        size_t i0 = ((size_t)(b * Hn + h) * DKn + d) * Sn + s;
                        g_Vh[i0] = h0; g_Vh[i0 + Sn] = h1;
                        g_Vl[i0] = l0; g_Vl[i0 + Sn] = l1;
                    } else {        // Q/K: s-major (B,H,S,DK)
                        size_t i0 = ((size_t)(b * Hn + h) * Sn + s) * DKn + d;
                        __nv_bfloat16* dh = (z == 0) ? g_Qh : g_Kh;
                        __nv_bfloat16* dl = (z == 0) ? g_Ql : g_Kl;
                        *(__nv_bfloat162*)&dh[i0] = __nv_bfloat162(h0, h1);
                        *(__nv_bfloat162*)&dl[i0] = __nv_bfloat162(l0, l1);
                    }
                }
            }
        }
}

// ==================== MMA flash attention ====================
// CTA: 128 q x KV loop of 128. 8 warps = 4(wm over q) x 2(wn over kv).
// Warp: S tile 32q x 64kv ; O tile 32q x 64d (partial over its kv half).
#define QKSB 144
#define VSB  272
#define oQh 0
#define oQl 18432
#define oKh 36864
#define oKl 55296
#define oVh 73728
#define oVl 91136
#define oRed 108544                 // redm[256], redl[256] f32
#define oStage 110592               // 128 x 64 f32
#define ATTN_SMEM (oStage + 128 * 64 * 4)   // 143360

__global__ __launch_bounds__(256, 1)
void attn_mma_kernel()
{
    extern __shared__ char sm[];
    const uint32_t sb = smem_to_u32(sm);
    float* redm = (float*)(sm + oRed);
    float* redl = (float*)(sm + oRed + 1024);
    float* stage = (float*)(sm + oStage);

    const int tid = threadIdx.x, wid = tid >> 5, lane = tid & 31;
    const int wm = wid >> 1, wn = wid & 1;
    const int q0 = blockIdx.x * 128;
    const int bh = blockIdx.y;
    const size_t base = (size_t)bh * Sn * DKn;

    const int rin = lane & 15;
    const int chf = lane >> 4;
    const int qr = lane >> 2, qc = (lane & 3) * 2;

    // load Q tile (128 x 64) hi/lo
#pragma unroll
    for (int i = 0; i < 4; i++) {
        int u = i * 256 + tid; int r = u >> 3; int c = u & 7;
        CP16(sb + oQh + r * QKSB + c * 16, g_Qh + base + (size_t)(q0 + r) * DKn + c * 8);
        CP16(sb + oQl + r * QKSB + c * 16, g_Ql + base + (size_t)(q0 + r) * DKn + c * 8);
    }
    CP_COMMIT();

    float acc_o[2][8][4];
    float m_st[2][2], l_st[2][2];
#pragma unroll
    for (int a = 0; a < 2; a++)
#pragma unroll
        for (int b = 0; b < 8; b++)
#pragma unroll
            for (int c = 0; c < 4; c++) acc_o[a][b][c] = 0.f;
#pragma unroll
    for (int a = 0; a < 2; a++)
#pragma unroll
        for (int b = 0; b < 2; b++) { m_st[a][b] = -1e30f; l_st[a][b] = 0.f; }

#pragma unroll 1
    for (int kv0 = 0; kv0 < Sn; kv0 += 128) {
        __syncthreads();   // everyone done with K/V/red of previous iter
        // K (128 x 64) hi/lo
#pragma unroll
        for (int i = 0; i < 4; i++) {
            int u = i * 256 + tid; int r = u >> 3; int c = u & 7;
            CP16(sb + oKh + r * QKSB + c * 16, g_Kh + base + (size_t)(kv0 + r) * DKn + c * 8);
            CP16(sb + oKl + r * QKSB + c * 16, g_Kl + base + (size_t)(kv0 + r) * DKn + c * 8);
        }
        // V d-major (64 x 128) hi/lo
#pragma unroll
        for (int i = 0; i < 4; i++) {
            int u = i * 256 + tid; int r = u >> 4; int c = u & 15;
            CP16(sb + oVh + r * VSB + c * 16, g_Vh + base + (size_t)r * Sn + kv0 + c * 8);
            CP16(sb + oVl + r * VSB + c * 16, g_Vl + base + (size_t)r * Sn + kv0 + c * 8);
        }
        CP_COMMIT();
        CP_WAIT0();
        __syncthreads();

        // ---- S = Q K^T ----
        float s[2][8][4];
#pragma unroll
        for (int a = 0; a < 2; a++)
#pragma unroll
            for (int b = 0; b < 8; b++)
#pragma unroll
                for (int c = 0; c < 4; c++) s[a][b][c] = 0.f;

#pragma unroll
        for (int ks = 0; ks < 4; ks++) {
            uint32_t qh_[2][4], ql_[2][4];
#pragma unroll
            for (int mt = 0; mt < 2; mt++) {
                uint32_t off = (uint32_t)((wm * 32 + mt * 16 + rin) * QKSB
                                          + (ks * 16 + chf * 8) * 2);
                ldsm4(sb + oQh + off, qh_[mt]);
                ldsm4(sb + oQl + off, ql_[mt]);
            }
            uint32_t kh_[4][4], kl_[4][4];
#pragma unroll
            for (int p = 0; p < 4; p++) {
                uint32_t off = (uint32_t)((wn * 64 + p * 16 + rin) * QKSB
                                          + (ks * 16 + chf * 8) * 2);
                ldsm4(sb + oKh + off, kh_[p]);
                ldsm4(sb + oKl + off, kl_[p]);
            }
#pragma unroll
            for (int mt = 0; mt < 2; mt++)
#pragma unroll
                for (int nt = 0; nt < 8; nt++) {
                    const int p = nt >> 1, e = nt & 1;
                    mma16816(s[mt][nt], qh_[mt], kh_[p][e], kh_[p][2 + e]);
                    mma16816(s[mt][nt], qh_[mt], kl_[p][e], kl_[p][2 + e]);
                    mma16816(s[mt][nt], ql_[mt], kh_[p][e], kh_[p][2 + e]);
                }
        }

        // ---- scale + row max (warp-local over 64 kv) ----
#pragma unroll
        for (int mt = 0; mt < 2; mt++)
#pragma unroll
            for (int hf = 0; hf < 2; hf++) {
                float mx = -1e30f;
#pragma unroll
                for (int nt = 0; nt < 8; nt++)
#pragma unroll
                    for (int e2 = 0; e2 < 2; e2++) {
                        float v = s[mt][nt][hf * 2 + e2] * 0.125f;
                        s[mt][nt][hf * 2 + e2] = v;
                        mx = fmaxf(mx, v);
                    }
                mx = fmaxf(mx, __shfl_xor_sync(0xffffffffu, mx, 1));
                mx = fmaxf(mx, __shfl_xor_sync(0xffffffffu, mx, 2));
                if ((lane & 3) == 0)
                    redm[(wm * 32 + mt * 16 + qr + hf * 8) * 2 + wn] = mx;
            }
        __syncthreads();

        float alpha_[2][2];
#pragma unroll
        for (int mt = 0; mt < 2; mt++)
#pragma unroll
            for (int hf = 0; hf < 2; hf++) {
                const int row = wm * 32 + mt * 16 + qr + hf * 8;
                float mx = fmaxf(redm[row * 2], redm[row * 2 + 1]);
                float mnew = fmaxf(m_st[mt][hf], mx);
                alpha_[mt][hf] = __expf(m_st[mt][hf] - mnew);
                m_st[mt][hf] = mnew;
                float sum = 0.f;
#pragma unroll
                for (int nt = 0; nt < 8; nt++)
#pragma unroll
                    for (int e2 = 0; e2 < 2; e2++) {
                        float p = __expf(s[mt][nt][hf * 2 + e2] - mnew);
                        s[mt][nt][hf * 2 + e2] = p;
                        sum += p;
                    }
                sum += __shfl_xor_sync(0xffffffffu, sum, 1);
                sum += __shfl_xor_sync(0xffffffffu, sum, 2);
                if ((lane & 3) == 0) redl[row * 2 + wn] = sum;
            }
        __syncthreads();
#pragma unroll
        for (int mt = 0; mt < 2; mt++)
#pragma unroll
            for (int hf = 0; hf < 2; hf++) {
                const int row = wm * 32 + mt * 16 + qr + hf * 8;
                l_st[mt][hf] = l_st[mt][hf] * alpha_[mt][hf]
                             + redl[row * 2] + redl[row * 2 + 1];
#pragma unroll
                for (int nt = 0; nt < 8; nt++) {
                    acc_o[mt][nt][hf * 2 + 0] *= alpha_[mt][hf];
                    acc_o[mt][nt][hf * 2 + 1] *= alpha_[mt][hf];
                }
            }

        // ---- O += P @ V (warp's 64-kv slice) ----
#pragma unroll
        for (int kc = 0; kc < 4; kc++) {
            uint32_t pa_h[2][4], pa_l[2][4];
#pragma unroll
            for (int mt = 0; mt < 2; mt++) {
                const float* s0 = s[mt][2 * kc];
                const float* s1 = s[mt][2 * kc + 1];
                packsplit(s0[0], s0[1], pa_h[mt][0], pa_l[mt][0]);
                packsplit(s0[2], s0[3], pa_h[mt][1], pa_l[mt][1]);
                packsplit(s1[0], s1[1], pa_h[mt][2], pa_l[mt][2]);
                packsplit(s1[2], s1[3], pa_h[mt][3], pa_l[mt][3]);
            }
            uint32_t vh_[4][4], vl_[4][4];
#pragma unroll
            for (int p = 0; p < 4; p++) {
                uint32_t off = (uint32_t)((p * 16 + rin) * VSB
                                          + (wn * 64 + kc * 16 + chf * 8) * 2);
                ldsm4(sb + oVh + off, vh_[p]);
                ldsm4(sb + oVl + off, vl_[p]);
            }
#pragma unroll
            for (int mt = 0; mt < 2; mt++)
#pragma unroll
                for (int nt = 0; nt < 8; nt++) {
                    const int p = nt >> 1, e = nt & 1;
                    mma16816(acc_o[mt][nt], pa_h[mt], vh_[p][e], vh_[p][2 + e]);
                    mma16816(acc_o[mt][nt], pa_h[mt], vl_[p][e], vl_[p][2 + e]);
                    mma16816(acc_o[mt][nt], pa_l[mt], vh_[p][e], vh_[p][2 + e]);
                }
        }
    }

    // ---- cross-warp (wn) merge + write ctx ----
    if (wn == 0) {
#pragma unroll
        for (int mt = 0; mt < 2; mt++)
#pragma unroll
            for (int hf = 0; hf < 2; hf++) {
                const int q = wm * 32 + mt * 16 + qr + hf * 8;
#pragma unroll
                for (int nt = 0; nt < 8; nt++) {
                    float2 v;
                    v.x = acc_o[mt][nt][hf * 2 + 0];
                    v.y = acc_o[mt][nt][hf * 2 + 1];
                    *(float2*)&stage[q * 64 + nt * 8 + qc] = v;
                }
            }
    }
    __syncthreads();
    if (wn == 1) {
        const int b = bh >> 4, h = bh & 15;
#pragma unroll
        for (int mt = 0; mt < 2; mt++)
#pragma unroll
            for (int hf = 0; hf < 2; hf++) {
                const int q = wm * 32 + mt * 16 + qr + hf * 8;
                const float rinv = 1.f / l_st[mt][hf];
#pragma unroll
                for (int nt = 0; nt < 8; nt++) {
                    float2 prev = *(const float2*)&stage[q * 64 + nt * 8 + qc];
                    float v0 = (prev.x + acc_o[mt][nt][hf * 2 + 0]) * rinv;
                    float v1 = (prev.y + acc_o[mt][nt][hf * 2 + 1]) * rinv;
                    __nv_bfloat16 h0, h1, l0, l1;
                    split2(v0, h0, l0); split2(v1, h1, l1);
                    size_t idx = ((size_t)b * Sn + q0 + q) * En + h * DKn + nt * 8 + qc;
                    *(__nv_bfloat162*)&g_Ch[idx] = __nv_bfloat162(h0, h1);
                    *(__nv_bfloat162*)&g_Cl[idx] = __nv_bfloat162(l0, l1);
                }
            }
    }
}

// ==================== launch ====================
extern "C" void kernel_launch(void* const* d_in, const int* in_sizes, int n_in,
                              void* d_out, int out_size)
{
    (void)in_sizes; (void)n_in; (void)out_size;
    const float* x  = (const float*)d_in[0];
    const float* Wq = (const float*)d_in[1];
    const float* Wk = (const float*)d_in[2];
    const float* Wv = (const float*)d_in[3];
    const float* Wo = (const float*)d_in[4];
    float* out = (float*)d_out;

    cudaFuncSetAttribute(gemm_mma_kernel,
                         cudaFuncAttributeMaxDynamicSharedMemorySize, GEMM_SMEM);
    cudaFuncSetAttribute(attn_mma_kernel,
                         cudaFuncAttributeMaxDynamicSharedMemorySize, ATTN_SMEM);

    split_kernel<<<Mn * En / 1024, 256>>>(x,  0, Mn * En / 4);
    split_kernel<<<En * En / 1024, 256>>>(Wq, 1, En * En / 4);
    split_kernel<<<En * En / 1024, 256>>>(Wk, 2, En * En / 4);
    split_kernel<<<En * En / 1024, 256>>>(Wv, 3, En * En / 4);
    split_kernel<<<En * En / 1024, 256>>>(Wo, 4, En * En / 4);

    dim3 gq(En / 128, Mn / 128, 3);
    gemm_mma_kernel<<<gq, 256, GEMM_SMEM>>>(0, nullptr);

    dim3 ga(Sn / 128, Bn * Hn);
    attn_mma_kernel<<<ga, 256, ATTN_SMEM>>>();

    dim3 go(En / 128, Mn / 128, 1);
    gemm_mma_kernel<<<go, 256, GEMM_SMEM>>>(1, out);
}

// round 5
// speedup vs baseline: 4.5353x; 1.4407x over previous
#include <cuda_runtime.h>
#include <cuda_bf16.h>
#include <cuda_fp16.h>
#include <cstdint>
#include <math.h>

#define Bn  4
#define Sn  2048
#define En  1024
#define Hn  16
#define DKn 64
#define Mn  (Bn * Sn)   // 8192

// ==================== device global scratch ====================
__device__ __nv_bfloat16 g_Xh[Mn * En], g_Xl[Mn * En];
__device__ __nv_bfloat16 g_Wh[4 * En * En], g_Wl[4 * En * En];
__device__ __half g_Qf[Mn * En];                 // (B,H,S,DK) fp16
__device__ __half g_Kf[Mn * En];                 // (B,H,S,DK) fp16
__device__ __half g_Vf[Mn * En];                 // (B,H,DK,S) fp16 d-major
__device__ __nv_bfloat16 g_Ch[Mn * En], g_Cl[Mn * En];   // ctx (B,S,E)

// ==================== helpers ====================
__device__ __forceinline__ uint32_t smem_to_u32(const void* p) {
    uint32_t a;
    asm("{ .reg .u64 t; cvta.to.shared.u64 t, %1; cvt.u32.u64 %0, t; }"
        : "=r"(a) : "l"(p));
    return a;
}
__device__ __forceinline__ void ldsm4(uint32_t addr, uint32_t r[4]) {
    asm volatile("ldmatrix.sync.aligned.m8n8.x4.shared.b16 {%0,%1,%2,%3}, [%4];"
                 : "=r"(r[0]), "=r"(r[1]), "=r"(r[2]), "=r"(r[3]) : "r"(addr));
}
__device__ __forceinline__ void mma16816(float d[4], const uint32_t a[4],
                                         uint32_t b0, uint32_t b1) {
    asm volatile(
        "mma.sync.aligned.m16n8k16.row.col.f32.bf16.bf16.f32 "
        "{%0,%1,%2,%3}, {%4,%5,%6,%7}, {%8,%9}, {%0,%1,%2,%3};"
        : "+f"(d[0]), "+f"(d[1]), "+f"(d[2]), "+f"(d[3])
        : "r"(a[0]), "r"(a[1]), "r"(a[2]), "r"(a[3]), "r"(b0), "r"(b1));
}
__device__ __forceinline__ void mma16816h(float d[4], const uint32_t a[4],
                                          uint32_t b0, uint32_t b1) {
    asm volatile(
        "mma.sync.aligned.m16n8k16.row.col.f32.f16.f16.f32 "
        "{%0,%1,%2,%3}, {%4,%5,%6,%7}, {%8,%9}, {%0,%1,%2,%3};"
        : "+f"(d[0]), "+f"(d[1]), "+f"(d[2]), "+f"(d[3])
        : "r"(a[0]), "r"(a[1]), "r"(a[2]), "r"(a[3]), "r"(b0), "r"(b1));
}
#define CP16(saddr, gptr) \
    asm volatile("cp.async.cg.shared.global [%0], [%1], 16;" \
                 :: "r"(saddr), "l"(gptr))
#define CP_COMMIT() asm volatile("cp.async.commit_group;")
#define CP_WAIT0()  asm volatile("cp.async.wait_group 0;")
#define CP_WAIT1()  asm volatile("cp.async.wait_group 1;")

// pack two f32 into f16x2 {lo=a, hi=b}
__device__ __forceinline__ uint32_t pack_f16x2(float a, float b) {
    uint32_t r;
    asm("cvt.rn.f16x2.f32 %0, %1, %2;" : "=r"(r) : "f"(b), "f"(a));
    return r;
}
__device__ __forceinline__ void split2(float v, __nv_bfloat16& h, __nv_bfloat16& l) {
    h = __float2bfloat16_rn(v);
    l = __float2bfloat16_rn(v - __bfloat162float(h));
}

// ==================== split fp32 -> bf16 hi/lo (all tensors, 1 launch) ======
#define NX4 (Mn * En / 4)   // 2097152
#define NW4 (En * En / 4)   // 262144
__global__ __launch_bounds__(256)
void split_all_kernel(const float* __restrict__ x,
                      const float* __restrict__ wq, const float* __restrict__ wk,
                      const float* __restrict__ wv, const float* __restrict__ wo)
{
    int i = blockIdx.x * blockDim.x + threadIdx.x;
    const float* src; __nv_bfloat16 *hi, *lo; int off;
    if (i < NX4) { src = x; hi = g_Xh; lo = g_Xl; off = i; }
    else {
        int j = i - NX4;
        int s = j >> 18;              // / NW4
        off = j & (NW4 - 1);
        src = (s == 0) ? wq : (s == 1) ? wk : (s == 2) ? wv : wo;
        hi = g_Wh + (size_t)s * En * En;
        lo = g_Wl + (size_t)s * En * En;
    }
    float4 v = ((const float4*)src)[off];
    __nv_bfloat16 h0, h1, h2, h3, l0, l1, l2, l3;
    split2(v.x, h0, l0); split2(v.y, h1, l1);
    split2(v.z, h2, l2); split2(v.w, h3, l3);
    ((__nv_bfloat162*)hi)[off * 2 + 0] = __nv_bfloat162(h0, h1);
    ((__nv_bfloat162*)hi)[off * 2 + 1] = __nv_bfloat162(h2, h3);
    ((__nv_bfloat162*)lo)[off * 2 + 0] = __nv_bfloat162(l0, l1);
    ((__nv_bfloat162*)lo)[off * 2 + 1] = __nv_bfloat162(l2, l3);
}

// ==================== MMA GEMM: Y = A @ W^T (bf16 3-product) ================
#define GSB  80
#define GT   (128 * GSB)
#define GEMM_SMEM (8 * GT)

#define GEMM_ISSUE(buf, k0) do {                                            \
    const __nv_bfloat16* _s[4] = { pA0, pA1, pB0, pB1 };                    \
    _Pragma("unroll")                                                       \
    for (int _t = 0; _t < 4; _t++) {                                        \
        uint32_t _db = sb + ((buf) * 4 + _t) * GT;                          \
        _Pragma("unroll")                                                   \
        for (int _i = 0; _i < 2; _i++) {                                    \
            int _u = _i * 256 + tid; int _r = _u >> 2; int _c = _u & 3;     \
            const void* _g = _s[_t] + (size_t)_r * En + (k0) + _c * 8;      \
            CP16(_db + _r * GSB + _c * 16, _g);                             \
        }                                                                   \
    }                                                                       \
    CP_COMMIT();                                                            \
} while (0)

__global__ __launch_bounds__(256, 1)
void gemm_mma_kernel(int mode, float* __restrict__ outp)
{
    extern __shared__ char sm[];
    const uint32_t sb = smem_to_u32(sm);
    const int tid = threadIdx.x, wid = tid >> 5, lane = tid & 31;
    const int wm = wid >> 2, wn = wid & 3;
    const int z = blockIdx.z;
    const int ws = (mode == 1) ? 3 : z;
    const int rowBase = blockIdx.y * 128, colBase = blockIdx.x * 128;

    const __nv_bfloat16* __restrict__ pA0 =
        (mode == 0 ? g_Xh : g_Ch) + (size_t)rowBase * En;
    const __nv_bfloat16* __restrict__ pA1 =
        (mode == 0 ? g_Xl : g_Cl) + (size_t)rowBase * En;
    const __nv_bfloat16* __restrict__ pB0 =
        g_Wh + (size_t)ws * En * En + (size_t)colBase * En;
    const __nv_bfloat16* __restrict__ pB1 =
        g_Wl + (size_t)ws * En * En + (size_t)colBase * En;

    float acc[4][4][4];
#pragma unroll
    for (int a = 0; a < 4; a++)
#pragma unroll
        for (int b = 0; b < 4; b++)
#pragma unroll
            for (int c = 0; c < 4; c++) acc[a][b][c] = 0.f;

    const int rin = lane & 15;
    const int chf = lane >> 4;

    GEMM_ISSUE(0, 0);
#pragma unroll 1
    for (int ch = 0; ch < 32; ch++) {
        const int buf = ch & 1;
        if (ch < 31) { GEMM_ISSUE(buf ^ 1, (ch + 1) * 32); CP_WAIT1(); }
        else         { CP_WAIT0(); }
        __syncthreads();
        const uint32_t aH = sb + (buf * 4 + 0) * GT;
        const uint32_t aL = sb + (buf * 4 + 1) * GT;
        const uint32_t bH = sb + (buf * 4 + 2) * GT;
        const uint32_t bL = sb + (buf * 4 + 3) * GT;

        uint32_t bf[2][2][2][4];
#pragma unroll
        for (int ks = 0; ks < 2; ks++)
#pragma unroll
            for (int p = 0; p < 2; p++) {
                uint32_t off = (uint32_t)((wn * 32 + p * 16 + rin) * GSB
                                          + (ks * 16 + chf * 8) * 2);
                ldsm4(bH + off, bf[0][ks][p]);
                ldsm4(bL + off, bf[1][ks][p]);
            }
#pragma unroll
        for (int mt = 0; mt < 4; mt++)
#pragma unroll
            for (int ks = 0; ks < 2; ks++) {
                uint32_t ah_[4], al_[4];
                uint32_t off = (uint32_t)((wm * 64 + mt * 16 + rin) * GSB
                                          + (ks * 16 + chf * 8) * 2);
                ldsm4(aH + off, ah_);
                ldsm4(aL + off, al_);
#pragma unroll
                for (int nt = 0; nt < 4; nt++) {
                    const int p = nt >> 1, e = nt & 1;
                    mma16816(acc[mt][nt], ah_, bf[0][ks][p][e], bf[0][ks][p][2 + e]);
                    mma16816(acc[mt][nt], ah_, bf[1][ks][p][e], bf[1][ks][p][2 + e]);
                    mma16816(acc[mt][nt], al_, bf[0][ks][p][e], bf[0][ks][p][2 + e]);
                }
            }
        __syncthreads();
    }

    const int qr = lane >> 2, qc = (lane & 3) * 2;
#pragma unroll
    for (int mt = 0; mt < 4; mt++)
#pragma unroll
        for (int hf = 0; hf < 2; hf++) {
            const int m = rowBase + wm * 64 + mt * 16 + qr + hf * 8;
#pragma unroll
            for (int nt = 0; nt < 4; nt++) {
                const int n = colBase + wn * 32 + nt * 8 + qc;
                const float v0 = acc[mt][nt][hf * 2 + 0];
                const float v1 = acc[mt][nt][hf * 2 + 1];
                if (mode == 1) {
                    float2 o; o.x = v0; o.y = v1;
                    *(float2*)&outp[(size_t)m * En + n] = o;
                } else {
                    const int b = m >> 11, s = m & (Sn - 1);
                    const int h = n >> 6,  d = n & 63;
                    __half h0 = __float2half_rn(v0);
                    __half h1 = __float2half_rn(v1);
                    if (z == 2) {   // V: d-major (B,H,DK,S)
                        size_t i0 = ((size_t)(b * Hn + h) * DKn + d) * Sn + s;
                        g_Vf[i0] = h0; g_Vf[i0 + Sn] = h1;
                    } else {        // Q/K: s-major (B,H,S,DK)
                        size_t i0 = ((size_t)(b * Hn + h) * Sn + s) * DKn + d;
                        __half* dst = (z == 0) ? g_Qf : g_Kf;
                        *(__half2*)&dst[i0] = __halves2half2(h0, h1);
                    }
                }
            }
        }
}

// ==================== MMA flash attention (fp16, double-buffered) ==========
// CTA: 128 q x kv tiles of 128. 8 warps = 4(wm) x 2(wn over kv halves).
#define QKSB 144                    // 64 fp16 = 128B + 16 pad
#define VSB  272                    // 128 fp16 = 256B + 16 pad
#define KBUF 18432                  // 128*QKSB
#define VBUF 17408                  // 64*VSB
#define oQ 0
#define oK 18432                    // 2 bufs
#define oV 55296                    // 2 bufs
#define oRed 90112                  // redm 1024 + redl 1024
#define oStage 92160                // 128*64*4 = 32768
#define ATTN_SMEM 124928

#define ISSUE_KV(buf, kv) do {                                              \
    uint32_t _kb = sb + oK + (buf) * KBUF;                                  \
    uint32_t _vb = sb + oV + (buf) * VBUF;                                  \
    _Pragma("unroll")                                                       \
    for (int _i = 0; _i < 4; _i++) {                                        \
        int _u = _i * 256 + tid; int _r = _u >> 3; int _c = _u & 7;         \
        CP16(_kb + _r * QKSB + _c * 16,                                     \
             g_Kf + base + (size_t)((kv) + _r) * DKn + _c * 8);             \
    }                                                                       \
    _Pragma("unroll")                                                       \
    for (int _i = 0; _i < 4; _i++) {                                        \
        int _u = _i * 256 + tid; int _r = _u >> 4; int _c = _u & 15;        \
        CP16(_vb + _r * VSB + _c * 16,                                      \
             g_Vf + base + (size_t)_r * Sn + (kv) + _c * 8);                \
    }                                                                       \
    CP_COMMIT();                                                            \
} while (0)

__global__ __launch_bounds__(256, 1)
void attn_mma_kernel()
{
    extern __shared__ char sm[];
    const uint32_t sb = smem_to_u32(sm);
    float* redm = (float*)(sm + oRed);
    float* redl = (float*)(sm + oRed + 1024);
    float* stage = (float*)(sm + oStage);

    const int tid = threadIdx.x, wid = tid >> 5, lane = tid & 31;
    const int wm = wid >> 1, wn = wid & 1;
    const int q0 = blockIdx.x * 128;
    const int bh = blockIdx.y;
    const size_t base = (size_t)bh * Sn * DKn;

    const int rin = lane & 15;
    const int chf = lane >> 4;
    const int qr = lane >> 2, qc = (lane & 3) * 2;

    // Q tile (128 x 64 fp16)
#pragma unroll
    for (int i = 0; i < 4; i++) {
        int u = i * 256 + tid; int r = u >> 3; int c = u & 7;
        CP16(sb + oQ + r * QKSB + c * 16,
             g_Qf + base + (size_t)(q0 + r) * DKn + c * 8);
    }
    CP_COMMIT();

    ISSUE_KV(0, 0);

    float acc_o[2][8][4];
    float m_st[2][2], l_st[2][2];
#pragma unroll
    for (int a = 0; a < 2; a++)
#pragma unroll
        for (int b = 0; b < 8; b++)
#pragma unroll
            for (int c = 0; c < 4; c++) acc_o[a][b][c] = 0.f;
#pragma unroll
    for (int a = 0; a < 2; a++)
#pragma unroll
        for (int b = 0; b < 2; b++) { m_st[a][b] = -1e30f; l_st[a][b] = 0.f; }

#pragma unroll 1
    for (int it = 0; it < 16; it++) {
        const int buf = it & 1;
        if (it < 15) { ISSUE_KV(buf ^ 1, (it + 1) * 128); CP_WAIT1(); }
        else         { CP_WAIT0(); }
        __syncthreads();
        const uint32_t kB = sb + oK + buf * KBUF;
        const uint32_t vB = sb + oV + buf * VBUF;

        // ---- S = Q K^T ----
        float s[2][8][4];
#pragma unroll
        for (int a = 0; a < 2; a++)
#pragma unroll
            for (int b = 0; b < 8; b++)
#pragma unroll
                for (int c = 0; c < 4; c++) s[a][b][c] = 0.f;

#pragma unroll
        for (int ks = 0; ks < 4; ks++) {
            uint32_t qf[2][4];
#pragma unroll
            for (int mt = 0; mt < 2; mt++) {
                uint32_t off = (uint32_t)((wm * 32 + mt * 16 + rin) * QKSB
                                          + (ks * 16 + chf * 8) * 2);
                ldsm4(sb + oQ + off, qf[mt]);
            }
            uint32_t kf[4][4];
#pragma unroll
            for (int p = 0; p < 4; p++) {
                uint32_t off = (uint32_t)((wn * 64 + p * 16 + rin) * QKSB
                                          + (ks * 16 + chf * 8) * 2);
                ldsm4(kB + off, kf[p]);
            }
#pragma unroll
            for (int mt = 0; mt < 2; mt++)
#pragma unroll
                for (int nt = 0; nt < 8; nt++) {
                    const int p = nt >> 1, e = nt & 1;
                    mma16816h(s[mt][nt], qf[mt], kf[p][e], kf[p][2 + e]);
                }
        }

        // ---- scale + row max ----
#pragma unroll
        for (int mt = 0; mt < 2; mt++)
#pragma unroll
            for (int hf = 0; hf < 2; hf++) {
                float mx = -1e30f;
#pragma unroll
                for (int nt = 0; nt < 8; nt++)
#pragma unroll
                    for (int e2 = 0; e2 < 2; e2++) {
                        float v = s[mt][nt][hf * 2 + e2] * 0.125f;
                        s[mt][nt][hf * 2 + e2] = v;
                        mx = fmaxf(mx, v);
                    }
                mx = fmaxf(mx, __shfl_xor_sync(0xffffffffu, mx, 1));
                mx = fmaxf(mx, __shfl_xor_sync(0xffffffffu, mx, 2));
                if ((lane & 3) == 0)
                    redm[(wm * 32 + mt * 16 + qr + hf * 8) * 2 + wn] = mx;
            }
        __syncthreads();

        float alpha_[2][2];
#pragma unroll
        for (int mt = 0; mt < 2; mt++)
#pragma unroll
            for (int hf = 0; hf < 2; hf++) {
                const int row = wm * 32 + mt * 16 + qr + hf * 8;
                float mx = fmaxf(redm[row * 2], redm[row * 2 + 1]);
                float mnew = fmaxf(m_st[mt][hf], mx);
                alpha_[mt][hf] = __expf(m_st[mt][hf] - mnew);
                m_st[mt][hf] = mnew;
                float sum = 0.f;
#pragma unroll
                for (int nt = 0; nt < 8; nt++)
#pragma unroll
                    for (int e2 = 0; e2 < 2; e2++) {
                        float p = __expf(s[mt][nt][hf * 2 + e2] - mnew);
                        s[mt][nt][hf * 2 + e2] = p;
                        sum += p;
                    }
                sum += __shfl_xor_sync(0xffffffffu, sum, 1);
                sum += __shfl_xor_sync(0xffffffffu, sum, 2);
                if ((lane & 3) == 0) redl[row * 2 + wn] = sum;
            }
        __syncthreads();
#pragma unroll
        for (int mt = 0; mt < 2; mt++)
#pragma unroll
            for (int hf = 0; hf < 2; hf++) {
                const int row = wm * 32 + mt * 16 + qr + hf * 8;
                l_st[mt][hf] = l_st[mt][hf] * alpha_[mt][hf]
                             + redl[row * 2] + redl[row * 2 + 1];
#pragma unroll
                for (int nt = 0; nt < 8; nt++) {
                    acc_o[mt][nt][hf * 2 + 0] *= alpha_[mt][hf];
                    acc_o[mt][nt][hf * 2 + 1] *= alpha_[mt][hf];
                }
            }

        // ---- O += P @ V ----
#pragma unroll
        for (int kc = 0; kc < 4; kc++) {
            uint32_t pa[2][4];
#pragma unroll
            for (int mt = 0; mt < 2; mt++) {
                const float* s0 = s[mt][2 * kc];
                const float* s1 = s[mt][2 * kc + 1];
                pa[mt][0] = pack_f16x2(s0[0], s0[1]);
                pa[mt][1] = pack_f16x2(s0[2], s0[3]);
                pa[mt][2] = pack_f16x2(s1[0], s1[1]);
                pa[mt][3] = pack_f16x2(s1[2], s1[3]);
            }
            uint32_t vf[4][4];
#pragma unroll
            for (int p = 0; p < 4; p++) {
                uint32_t off = (uint32_t)((p * 16 + rin) * VSB
                                          + (wn * 64 + kc * 16 + chf * 8) * 2);
                ldsm4(vB + off, vf[p]);
            }
#pragma unroll
            for (int mt = 0; mt < 2; mt++)
#pragma unroll
                for (int nt = 0; nt < 8; nt++) {
                    const int p = nt >> 1, e = nt & 1;
                    mma16816h(acc_o[mt][nt], pa[mt], vf[p][e], vf[p][2 + e]);
                }
        }
        __syncthreads();
    }

    // ---- cross-warp (wn) merge + write ctx hi/lo bf16 ----
    if (wn == 0) {
#pragma unroll
        for (int mt = 0; mt < 2; mt++)
#pragma unroll
            for (int hf = 0; hf < 2; hf++) {
                const int q = wm * 32 + mt * 16 + qr + hf * 8;
#pragma unroll
                for (int nt = 0; nt < 8; nt++) {
                    float2 v;
                    v.x = acc_o[mt][nt][hf * 2 + 0];
                    v.y = acc_o[mt][nt][hf * 2 + 1];
                    *(float2*)&stage[q * 64 + nt * 8 + qc] = v;
                }
            }
    }
    __syncthreads();
    if (wn == 1) {
        const int b = bh >> 4, h = bh & 15;
#pragma unroll
        for (int mt = 0; mt < 2; mt++)
#pragma unroll
            for (int hf = 0; hf < 2; hf++) {
                const int q = wm * 32 + mt * 16 + qr + hf * 8;
                const float rinv = 1.f / l_st[mt][hf];
#pragma unroll
                for (int nt = 0; nt < 8; nt++) {
                    float2 prev = *(const float2*)&stage[q * 64 + nt * 8 + qc];
                    float v0 = (prev.x + acc_o[mt][nt][hf * 2 + 0]) * rinv;
                    float v1 = (prev.y + acc_o[mt][nt][hf * 2 + 1]) * rinv;
                    __nv_bfloat16 h0, h1, l0, l1;
                    split2(v0, h0, l0); split2(v1, h1, l1);
                    size_t idx = ((size_t)b * Sn + q0 + q) * En + h * DKn + nt * 8 + qc;
                    *(__nv_bfloat162*)&g_Ch[idx] = __nv_bfloat162(h0, h1);
                    *(__nv_bfloat162*)&g_Cl[idx] = __nv_bfloat162(l0, l1);
                }
            }
    }
}

// ==================== launch ====================
extern "C" void kernel_launch(void* const* d_in, const int* in_sizes, int n_in,
                              void* d_out, int out_size)
{
    (void)in_sizes; (void)n_in; (void)out_size;
    const float* x  = (const float*)d_in[0];
    const float* Wq = (const float*)d_in[1];
    const float* Wk = (const float*)d_in[2];
    const float* Wv = (const float*)d_in[3];
    const float* Wo = (const float*)d_in[4];
    float* out = (float*)d_out;

    cudaFuncSetAttribute(gemm_mma_kernel,
                         cudaFuncAttributeMaxDynamicSharedMemorySize, GEMM_SMEM);
    cudaFuncSetAttribute(attn_mma_kernel,
                         cudaFuncAttributeMaxDynamicSharedMemorySize, ATTN_SMEM);

    split_all_kernel<<<(NX4 + 4 * NW4) / 256, 256>>>(x, Wq, Wk, Wv, Wo);

    dim3 gq(En / 128, Mn / 128, 3);
    gemm_mma_kernel<<<gq, 256, GEMM_SMEM>>>(0, nullptr);

    dim3 ga(Sn / 128, Bn * Hn);
    attn_mma_kernel<<<ga, 256, ATTN_SMEM>>>();

    dim3 go(En / 128, Mn / 128, 1);
    gemm_mma_kernel<<<go, 256, GEMM_SMEM>>>(1, out);
}

// round 6
// speedup vs baseline: 6.5610x; 1.4466x over previous
#include <cuda_runtime.h>
#include <cuda_bf16.h>
#include <cuda_fp16.h>
#include <cstdint>
#include <math.h>

#define Bn  4
#define Sn  2048
#define En  1024
#define Hn  16
#define DKn 64
#define Mn  (Bn * Sn)   // 8192

// ==================== device global scratch ====================
__device__ __half g_Xf[Mn * En];                  // x fp16
__device__ __half g_Wf[3 * En * En];              // Wq,Wk,Wv fp16
__device__ __nv_bfloat16 g_Woh[En * En], g_Wol[En * En];
__device__ __half g_Qf[Mn * En];                  // (B,H,S,DK)
__device__ __half g_Kf[Mn * En];                  // (B,H,S,DK)
__device__ __half g_Vf[Mn * En];                  // (B,H,DK,S) d-major
__device__ __nv_bfloat16 g_Ch[Mn * En], g_Cl[Mn * En];   // ctx (B,S,E)

// ==================== helpers ====================
__device__ __forceinline__ uint32_t smem_to_u32(const void* p) {
    uint32_t a;
    asm("{ .reg .u64 t; cvta.to.shared.u64 t, %1; cvt.u32.u64 %0, t; }"
        : "=r"(a) : "l"(p));
    return a;
}
__device__ __forceinline__ void ldsm4(uint32_t addr, uint32_t r[4]) {
    asm volatile("ldmatrix.sync.aligned.m8n8.x4.shared.b16 {%0,%1,%2,%3}, [%4];"
                 : "=r"(r[0]), "=r"(r[1]), "=r"(r[2]), "=r"(r[3]) : "r"(addr));
}
__device__ __forceinline__ void mma16816(float d[4], const uint32_t a[4],
                                         uint32_t b0, uint32_t b1) {
    asm volatile(
        "mma.sync.aligned.m16n8k16.row.col.f32.bf16.bf16.f32 "
        "{%0,%1,%2,%3}, {%4,%5,%6,%7}, {%8,%9}, {%0,%1,%2,%3};"
        : "+f"(d[0]), "+f"(d[1]), "+f"(d[2]), "+f"(d[3])
        : "r"(a[0]), "r"(a[1]), "r"(a[2]), "r"(a[3]), "r"(b0), "r"(b1));
}
__device__ __forceinline__ void mma16816h(float d[4], const uint32_t a[4],
                                          uint32_t b0, uint32_t b1) {
    asm volatile(
        "mma.sync.aligned.m16n8k16.row.col.f32.f16.f16.f32 "
        "{%0,%1,%2,%3}, {%4,%5,%6,%7}, {%8,%9}, {%0,%1,%2,%3};"
        : "+f"(d[0]), "+f"(d[1]), "+f"(d[2]), "+f"(d[3])
        : "r"(a[0]), "r"(a[1]), "r"(a[2]), "r"(a[3]), "r"(b0), "r"(b1));
}
#define CP16(saddr, gptr) \
    asm volatile("cp.async.cg.shared.global [%0], [%1], 16;" \
                 :: "r"(saddr), "l"(gptr))
#define CP_COMMIT() asm volatile("cp.async.commit_group;")
#define CP_WAIT0()  asm volatile("cp.async.wait_group 0;")
#define CP_WAIT1()  asm volatile("cp.async.wait_group 1;")

__device__ __forceinline__ uint32_t pack_f16x2(float a, float b) {
    uint32_t r;
    asm("cvt.rn.f16x2.f32 %0, %1, %2;" : "=r"(r) : "f"(b), "f"(a));
    return r;
}
__device__ __forceinline__ void split2(float v, __nv_bfloat16& h, __nv_bfloat16& l) {
    h = __float2bfloat16_rn(v);
    l = __float2bfloat16_rn(v - __bfloat162float(h));
}

// ==================== split / convert inputs (1 launch) ====================
#define NX4 (Mn * En / 4)   // 2097152
#define NW4 (En * En / 4)   // 262144 = 2^18
__global__ __launch_bounds__(256)
void split_all_kernel(const float* __restrict__ x,
                      const float* __restrict__ wq, const float* __restrict__ wk,
                      const float* __restrict__ wv, const float* __restrict__ wo)
{
    int i = blockIdx.x * blockDim.x + threadIdx.x;
    if (i < NX4) {
        float4 v = ((const float4*)x)[i];
        __half2 a = __halves2half2(__float2half_rn(v.x), __float2half_rn(v.y));
        __half2 b = __halves2half2(__float2half_rn(v.z), __float2half_rn(v.w));
        ((__half2*)g_Xf)[i * 2 + 0] = a;
        ((__half2*)g_Xf)[i * 2 + 1] = b;
        return;
    }
    int j = i - NX4;
    int s = j >> 18;
    int off = j & (NW4 - 1);
    if (s < 3) {
        const float* src = (s == 0) ? wq : (s == 1) ? wk : wv;
        float4 v = ((const float4*)src)[off];
        __half* dst = g_Wf + (size_t)s * En * En;
        ((__half2*)dst)[off * 2 + 0] =
            __halves2half2(__float2half_rn(v.x), __float2half_rn(v.y));
        ((__half2*)dst)[off * 2 + 1] =
            __halves2half2(__float2half_rn(v.z), __float2half_rn(v.w));
    } else {
        float4 v = ((const float4*)wo)[off];
        __nv_bfloat16 h0, h1, h2, h3, l0, l1, l2, l3;
        split2(v.x, h0, l0); split2(v.y, h1, l1);
        split2(v.z, h2, l2); split2(v.w, h3, l3);
        ((__nv_bfloat162*)g_Woh)[off * 2 + 0] = __nv_bfloat162(h0, h1);
        ((__nv_bfloat162*)g_Woh)[off * 2 + 1] = __nv_bfloat162(h2, h3);
        ((__nv_bfloat162*)g_Wol)[off * 2 + 0] = __nv_bfloat162(l0, l1);
        ((__nv_bfloat162*)g_Wol)[off * 2 + 1] = __nv_bfloat162(l2, l3);
    }
}

// ==================== QKV GEMM (fp16 single-product) ====================
// 128x128 tile, 8 warps (wm2 x wn4), warp 64x32, BK=64, double buffer.
#define QGSB 144                 // 64 fp16 = 128B + 16 pad
#define QGT  (128 * QGSB)        // 18432
#define QKV_SMEM (4 * QGT)       // 73728 (A,B x 2 buffers)

#define QKV_ISSUE(buf, k0) do {                                             \
    _Pragma("unroll")                                                       \
    for (int _t = 0; _t < 2; _t++) {                                        \
        const __half* _src = (_t == 0) ? pA : pB;                           \
        uint32_t _db = sb + ((buf) * 2 + _t) * QGT;                         \
        _Pragma("unroll")                                                   \
        for (int _i = 0; _i < 4; _i++) {                                    \
            int _u = _i * 256 + tid; int _r = _u >> 3; int _c = _u & 7;     \
            CP16(_db + _r * QGSB + _c * 16,                                 \
                 _src + (size_t)_r * En + (k0) + _c * 8);                   \
        }                                                                   \
    }                                                                       \
    CP_COMMIT();                                                            \
} while (0)

__global__ __launch_bounds__(256, 2)
void gemm_qkv_f16(void)
{
    extern __shared__ char sm[];
    const uint32_t sb = smem_to_u32(sm);
    const int tid = threadIdx.x, wid = tid >> 5, lane = tid & 31;
    const int wm = wid >> 2, wn = wid & 3;
    const int z = blockIdx.z;
    const int rowBase = blockIdx.y * 128, colBase = blockIdx.x * 128;

    const __half* __restrict__ pA = g_Xf + (size_t)rowBase * En;
    const __half* __restrict__ pB = g_Wf + (size_t)z * En * En + (size_t)colBase * En;

    float acc[4][4][4];
#pragma unroll
    for (int a = 0; a < 4; a++)
#pragma unroll
        for (int b = 0; b < 4; b++)
#pragma unroll
            for (int c = 0; c < 4; c++) acc[a][b][c] = 0.f;

    const int rin = lane & 15;
    const int chf = lane >> 4;

    QKV_ISSUE(0, 0);
#pragma unroll 1
    for (int ch = 0; ch < 16; ch++) {
        const int buf = ch & 1;
        if (ch < 15) { QKV_ISSUE(buf ^ 1, (ch + 1) * 64); CP_WAIT1(); }
        else         { CP_WAIT0(); }
        __syncthreads();
        const uint32_t aB = sb + (buf * 2 + 0) * QGT;
        const uint32_t bB = sb + (buf * 2 + 1) * QGT;

#pragma unroll
        for (int ks = 0; ks < 4; ks++) {
            uint32_t kf[2][4];
#pragma unroll
            for (int p = 0; p < 2; p++) {
                uint32_t off = (uint32_t)((wn * 32 + p * 16 + rin) * QGSB
                                          + (ks * 16 + chf * 8) * 2);
                ldsm4(bB + off, kf[p]);
            }
#pragma unroll
            for (int mt = 0; mt < 4; mt++) {
                uint32_t af[4];
                uint32_t off = (uint32_t)((wm * 64 + mt * 16 + rin) * QGSB
                                          + (ks * 16 + chf * 8) * 2);
                ldsm4(aB + off, af);
#pragma unroll
                for (int nt = 0; nt < 4; nt++) {
                    const int p = nt >> 1, e = nt & 1;
                    mma16816h(acc[mt][nt], af, kf[p][e], kf[p][2 + e]);
                }
            }
        }
        __syncthreads();
    }

    // epilogue: Q/K s-major fp16, V d-major fp16
    const int qr = lane >> 2, qc = (lane & 3) * 2;
#pragma unroll
    for (int mt = 0; mt < 4; mt++)
#pragma unroll
        for (int hf = 0; hf < 2; hf++) {
            const int m = rowBase + wm * 64 + mt * 16 + qr + hf * 8;
            const int b = m >> 11, s = m & (Sn - 1);
#pragma unroll
            for (int nt = 0; nt < 4; nt++) {
                const int n = colBase + wn * 32 + nt * 8 + qc;
                const int h = n >> 6, d = n & 63;
                __half h0 = __float2half_rn(acc[mt][nt][hf * 2 + 0]);
                __half h1 = __float2half_rn(acc[mt][nt][hf * 2 + 1]);
                if (z == 2) {
                    size_t i0 = ((size_t)(b * Hn + h) * DKn + d) * Sn + s;
                    g_Vf[i0] = h0; g_Vf[i0 + Sn] = h1;
                } else {
                    size_t i0 = ((size_t)(b * Hn + h) * Sn + s) * DKn + d;
                    __half* dst = (z == 0) ? g_Qf : g_Kf;
                    *(__half2*)&dst[i0] = __halves2half2(h0, h1);
                }
            }
        }
}

// ==================== Wo GEMM (bf16 3-product, reordered) ====================
#define GSB  80
#define GT   (128 * GSB)
#define GEMM_SMEM (8 * GT)

#define GEMM_ISSUE(buf, k0) do {                                            \
    const __nv_bfloat16* _s[4] = { pA0, pA1, pB0, pB1 };                    \
    _Pragma("unroll")                                                       \
    for (int _t = 0; _t < 4; _t++) {                                        \
        uint32_t _db = sb + ((buf) * 4 + _t) * GT;                          \
        _Pragma("unroll")                                                   \
        for (int _i = 0; _i < 2; _i++) {                                    \
            int _u = _i * 256 + tid; int _r = _u >> 2; int _c = _u & 3;     \
            const void* _g = _s[_t] + (size_t)_r * En + (k0) + _c * 8;      \
            CP16(_db + _r * GSB + _c * 16, _g);                             \
        }                                                                   \
    }                                                                       \
    CP_COMMIT();                                                            \
} while (0)

__global__ __launch_bounds__(256, 2)
void gemm_wo_kernel(float* __restrict__ outp)
{
    extern __shared__ char sm[];
    const uint32_t sb = smem_to_u32(sm);
    const int tid = threadIdx.x, wid = tid >> 5, lane = tid & 31;
    const int wm = wid >> 2, wn = wid & 3;
    const int rowBase = blockIdx.y * 128, colBase = blockIdx.x * 128;

    const __nv_bfloat16* __restrict__ pA0 = g_Ch + (size_t)rowBase * En;
    const __nv_bfloat16* __restrict__ pA1 = g_Cl + (size_t)rowBase * En;
    const __nv_bfloat16* __restrict__ pB0 = g_Woh + (size_t)colBase * En;
    const __nv_bfloat16* __restrict__ pB1 = g_Wol + (size_t)colBase * En;

    float acc[4][4][4];
#pragma unroll
    for (int a = 0; a < 4; a++)
#pragma unroll
        for (int b = 0; b < 4; b++)
#pragma unroll
            for (int c = 0; c < 4; c++) acc[a][b][c] = 0.f;

    const int rin = lane & 15;
    const int chf = lane >> 4;

    GEMM_ISSUE(0, 0);
#pragma unroll 1
    for (int ch = 0; ch < 32; ch++) {
        const int buf = ch & 1;
        if (ch < 31) { GEMM_ISSUE(buf ^ 1, (ch + 1) * 32); CP_WAIT1(); }
        else         { CP_WAIT0(); }
        __syncthreads();
        const uint32_t aH = sb + (buf * 4 + 0) * GT;
        const uint32_t aL = sb + (buf * 4 + 1) * GT;
        const uint32_t bH = sb + (buf * 4 + 2) * GT;
        const uint32_t bL = sb + (buf * 4 + 3) * GT;

        uint32_t bf[2][2][2][4];   // [hl][ks][p][4]
#pragma unroll
        for (int ks = 0; ks < 2; ks++)
#pragma unroll
            for (int p = 0; p < 2; p++) {
                uint32_t off = (uint32_t)((wn * 32 + p * 16 + rin) * GSB
                                          + (ks * 16 + chf * 8) * 2);
                ldsm4(bH + off, bf[0][ks][p]);
                ldsm4(bL + off, bf[1][ks][p]);
            }
#pragma unroll
        for (int mt = 0; mt < 4; mt++) {
            uint32_t ah_[2][4], al_[2][4];
#pragma unroll
            for (int ks = 0; ks < 2; ks++) {
                uint32_t off = (uint32_t)((wm * 64 + mt * 16 + rin) * GSB
                                          + (ks * 16 + chf * 8) * 2);
                ldsm4(aH + off, ah_[ks]);
                ldsm4(aL + off, al_[ks]);
            }
            // pass 1: Ah x Bh
#pragma unroll
            for (int ks = 0; ks < 2; ks++)
#pragma unroll
                for (int nt = 0; nt < 4; nt++) {
                    const int p = nt >> 1, e = nt & 1;
                    mma16816(acc[mt][nt], ah_[ks], bf[0][ks][p][e], bf[0][ks][p][2 + e]);
                }
            // pass 2: Ah x Bl
#pragma unroll
            for (int ks = 0; ks < 2; ks++)
#pragma unroll
                for (int nt = 0; nt < 4; nt++) {
                    const int p = nt >> 1, e = nt & 1;
                    mma16816(acc[mt][nt], ah_[ks], bf[1][ks][p][e], bf[1][ks][p][2 + e]);
                }
            // pass 3: Al x Bh
#pragma unroll
            for (int ks = 0; ks < 2; ks++)
#pragma unroll
                for (int nt = 0; nt < 4; nt++) {
                    const int p = nt >> 1, e = nt & 1;
                    mma16816(acc[mt][nt], al_[ks], bf[0][ks][p][e], bf[0][ks][p][2 + e]);
                }
        }
        __syncthreads();
    }

    const int qr = lane >> 2, qc = (lane & 3) * 2;
#pragma unroll
    for (int mt = 0; mt < 4; mt++)
#pragma unroll
        for (int hf = 0; hf < 2; hf++) {
            const int m = rowBase + wm * 64 + mt * 16 + qr + hf * 8;
#pragma unroll
            for (int nt = 0; nt < 4; nt++) {
                const int n = colBase + wn * 32 + nt * 8 + qc;
                float2 o;
                o.x = acc[mt][nt][hf * 2 + 0];
                o.y = acc[mt][nt][hf * 2 + 1];
                *(float2*)&outp[(size_t)m * En + n] = o;
            }
        }
}

// ==================== MMA flash attention (fp16, double-buffered) ==========
#define QKSB 144
#define VSB  272
#define KBUF 18432
#define VBUF 17408
#define oQ 0
#define oK 18432
#define oV 55296
#define oRed 90112
#define oStage 92160
#define ATTN_SMEM 124928

#define ISSUE_KV(buf, kv) do {                                              \
    uint32_t _kb = sb + oK + (buf) * KBUF;                                  \
    uint32_t _vb = sb + oV + (buf) * VBUF;                                  \
    _Pragma("unroll")                                                       \
    for (int _i = 0; _i < 4; _i++) {                                        \
        int _u = _i * 256 + tid; int _r = _u >> 3; int _c = _u & 7;         \
        CP16(_kb + _r * QKSB + _c * 16,                                     \
             g_Kf + base + (size_t)((kv) + _r) * DKn + _c * 8);             \
    }                                                                       \
    _Pragma("unroll")                                                       \
    for (int _i = 0; _i < 4; _i++) {                                        \
        int _u = _i * 256 + tid; int _r = _u >> 4; int _c = _u & 15;        \
        CP16(_vb + _r * VSB + _c * 16,                                      \
             g_Vf + base + (size_t)_r * Sn + (kv) + _c * 8);                \
    }                                                                       \
    CP_COMMIT();                                                            \
} while (0)

__global__ __launch_bounds__(256, 1)
void attn_mma_kernel()
{
    extern __shared__ char sm[];
    const uint32_t sb = smem_to_u32(sm);
    float* redm = (float*)(sm + oRed);
    float* redl = (float*)(sm + oRed + 1024);
    float* stage = (float*)(sm + oStage);

    const int tid = threadIdx.x, wid = tid >> 5, lane = tid & 31;
    const int wm = wid >> 1, wn = wid & 1;
    const int q0 = blockIdx.x * 128;
    const int bh = blockIdx.y;
    const size_t base = (size_t)bh * Sn * DKn;

    const int rin = lane & 15;
    const int chf = lane >> 4;
    const int qr = lane >> 2, qc = (lane & 3) * 2;

#pragma unroll
    for (int i = 0; i < 4; i++) {
        int u = i * 256 + tid; int r = u >> 3; int c = u & 7;
        CP16(sb + oQ + r * QKSB + c * 16,
             g_Qf + base + (size_t)(q0 + r) * DKn + c * 8);
    }
    CP_COMMIT();

    ISSUE_KV(0, 0);

    float acc_o[2][8][4];
    float m_st[2][2], l_st[2][2];
#pragma unroll
    for (int a = 0; a < 2; a++)
#pragma unroll
        for (int b = 0; b < 8; b++)
#pragma unroll
            for (int c = 0; c < 4; c++) acc_o[a][b][c] = 0.f;
#pragma unroll
    for (int a = 0; a < 2; a++)
#pragma unroll
        for (int b = 0; b < 2; b++) { m_st[a][b] = -1e30f; l_st[a][b] = 0.f; }

#pragma unroll 1
    for (int it = 0; it < 16; it++) {
        const int buf = it & 1;
        if (it < 15) { ISSUE_KV(buf ^ 1, (it + 1) * 128); CP_WAIT1(); }
        else         { CP_WAIT0(); }
        __syncthreads();
        const uint32_t kB = sb + oK + buf * KBUF;
        const uint32_t vB = sb + oV + buf * VBUF;

        float s[2][8][4];
#pragma unroll
        for (int a = 0; a < 2; a++)
#pragma unroll
            for (int b = 0; b < 8; b++)
#pragma unroll
                for (int c = 0; c < 4; c++) s[a][b][c] = 0.f;

#pragma unroll
        for (int ks = 0; ks < 4; ks++) {
            uint32_t qf[2][4];
#pragma unroll
            for (int mt = 0; mt < 2; mt++) {
                uint32_t off = (uint32_t)((wm * 32 + mt * 16 + rin) * QKSB
                                          + (ks * 16 + chf * 8) * 2);
                ldsm4(sb + oQ + off, qf[mt]);
            }
            uint32_t kf[4][4];
#pragma unroll
            for (int p = 0; p < 4; p++) {
                uint32_t off = (uint32_t)((wn * 64 + p * 16 + rin) * QKSB
                                          + (ks * 16 + chf * 8) * 2);
                ldsm4(kB + off, kf[p]);
            }
#pragma unroll
            for (int mt = 0; mt < 2; mt++)
#pragma unroll
                for (int nt = 0; nt < 8; nt++) {
                    const int p = nt >> 1, e = nt & 1;
                    mma16816h(s[mt][nt], qf[mt], kf[p][e], kf[p][2 + e]);
                }
        }

#pragma unroll
        for (int mt = 0; mt < 2; mt++)
#pragma unroll
            for (int hf = 0; hf < 2; hf++) {
                float mx = -1e30f;
#pragma unroll
                for (int nt = 0; nt < 8; nt++)
#pragma unroll
                    for (int e2 = 0; e2 < 2; e2++) {
                        float v = s[mt][nt][hf * 2 + e2] * 0.125f;
                        s[mt][nt][hf * 2 + e2] = v;
                        mx = fmaxf(mx, v);
                    }
                mx = fmaxf(mx, __shfl_xor_sync(0xffffffffu, mx, 1));
                mx = fmaxf(mx, __shfl_xor_sync(0xffffffffu, mx, 2));
                if ((lane & 3) == 0)
                    redm[(wm * 32 + mt * 16 + qr + hf * 8) * 2 + wn] = mx;
            }
        __syncthreads();

        float alpha_[2][2];
#pragma unroll
        for (int mt = 0; mt < 2; mt++)
#pragma unroll
            for (int hf = 0; hf < 2; hf++) {
                const int row = wm * 32 + mt * 16 + qr + hf * 8;
                float mx = fmaxf(redm[row * 2], redm[row * 2 + 1]);
                float mnew = fmaxf(m_st[mt][hf], mx);
                alpha_[mt][hf] = __expf(m_st[mt][hf] - mnew);
                m_st[mt][hf] = mnew;
                float sum = 0.f;
#pragma unroll
                for (int nt = 0; nt < 8; nt++)
#pragma unroll
                    for (int e2 = 0; e2 < 2; e2++) {
                        float p = __expf(s[mt][nt][hf * 2 + e2] - mnew);
                        s[mt][nt][hf * 2 + e2] = p;
                        sum += p;
                    }
                sum += __shfl_xor_sync(0xffffffffu, sum, 1);
                sum += __shfl_xor_sync(0xffffffffu, sum, 2);
                if ((lane & 3) == 0) redl[row * 2 + wn] = sum;
            }
        __syncthreads();
#pragma unroll
        for (int mt = 0; mt < 2; mt++)
#pragma unroll
            for (int hf = 0; hf < 2; hf++) {
                const int row = wm * 32 + mt * 16 + qr + hf * 8;
                l_st[mt][hf] = l_st[mt][hf] * alpha_[mt][hf]
                             + redl[row * 2] + redl[row * 2 + 1];
#pragma unroll
                for (int nt = 0; nt < 8; nt++) {
                    acc_o[mt][nt][hf * 2 + 0] *= alpha_[mt][hf];
                    acc_o[mt][nt][hf * 2 + 1] *= alpha_[mt][hf];
                }
            }

#pragma unroll
        for (int kc = 0; kc < 4; kc++) {
            uint32_t pa[2][4];
#pragma unroll
            for (int mt = 0; mt < 2; mt++) {
                const float* s0 = s[mt][2 * kc];
                const float* s1 = s[mt][2 * kc + 1];
                pa[mt][0] = pack_f16x2(s0[0], s0[1]);
                pa[mt][1] = pack_f16x2(s0[2], s0[3]);
                pa[mt][2] = pack_f16x2(s1[0], s1[1]);
                pa[mt][3] = pack_f16x2(s1[2], s1[3]);
            }
            uint32_t vf[4][4];
#pragma unroll
            for (int p = 0; p < 4; p++) {
                uint32_t off = (uint32_t)((p * 16 + rin) * VSB
                                          + (wn * 64 + kc * 16 + chf * 8) * 2);
                ldsm4(vB + off, vf[p]);
            }
#pragma unroll
            for (int mt = 0; mt < 2; mt++)
#pragma unroll
                for (int nt = 0; nt < 8; nt++) {
                    const int p = nt >> 1, e = nt & 1;
                    mma16816h(acc_o[mt][nt], pa[mt], vf[p][e], vf[p][2 + e]);
                }
        }
        __syncthreads();
    }

    if (wn == 0) {
#pragma unroll
        for (int mt = 0; mt < 2; mt++)
#pragma unroll
            for (int hf = 0; hf < 2; hf++) {
                const int q = wm * 32 + mt * 16 + qr + hf * 8;
#pragma unroll
                for (int nt = 0; nt < 8; nt++) {
                    float2 v;
                    v.x = acc_o[mt][nt][hf * 2 + 0];
                    v.y = acc_o[mt][nt][hf * 2 + 1];
                    *(float2*)&stage[q * 64 + nt * 8 + qc] = v;
                }
            }
    }
    __syncthreads();
    if (wn == 1) {
        const int b = bh >> 4, h = bh & 15;
#pragma unroll
        for (int mt = 0; mt < 2; mt++)
#pragma unroll
            for (int hf = 0; hf < 2; hf++) {
                const int q = wm * 32 + mt * 16 + qr + hf * 8;
                const float rinv = 1.f / l_st[mt][hf];
#pragma unroll
                for (int nt = 0; nt < 8; nt++) {
                    float2 prev = *(const float2*)&stage[q * 64 + nt * 8 + qc];
                    float v0 = (prev.x + acc_o[mt][nt][hf * 2 + 0]) * rinv;
                    float v1 = (prev.y + acc_o[mt][nt][hf * 2 + 1]) * rinv;
                    __nv_bfloat16 h0, h1, l0, l1;
                    split2(v0, h0, l0); split2(v1, h1, l1);
                    size_t idx = ((size_t)b * Sn + q0 + q) * En + h * DKn + nt * 8 + qc;
                    *(__nv_bfloat162*)&g_Ch[idx] = __nv_bfloat162(h0, h1);
                    *(__nv_bfloat162*)&g_Cl[idx] = __nv_bfloat162(l0, l1);
                }
            }
    }
}

// ==================== launch ====================
extern "C" void kernel_launch(void* const* d_in, const int* in_sizes, int n_in,
                              void* d_out, int out_size)
{
    (void)in_sizes; (void)n_in; (void)out_size;
    const float* x  = (const float*)d_in[0];
    const float* Wq = (const float*)d_in[1];
    const float* Wk = (const float*)d_in[2];
    const float* Wv = (const float*)d_in[3];
    const float* Wo = (const float*)d_in[4];
    float* out = (float*)d_out;

    cudaFuncSetAttribute(gemm_qkv_f16,
                         cudaFuncAttributeMaxDynamicSharedMemorySize, QKV_SMEM);
    cudaFuncSetAttribute(gemm_wo_kernel,
                         cudaFuncAttributeMaxDynamicSharedMemorySize, GEMM_SMEM);
    cudaFuncSetAttribute(attn_mma_kernel,
                         cudaFuncAttributeMaxDynamicSharedMemorySize, ATTN_SMEM);

    split_all_kernel<<<(NX4 + 4 * NW4) / 256, 256>>>(x, Wq, Wk, Wv, Wo);

    dim3 gq(En / 128, Mn / 128, 3);
    gemm_qkv_f16<<<gq, 256, QKV_SMEM>>>();

    dim3 ga(Sn / 128, Bn * Hn);
    attn_mma_kernel<<<ga, 256, ATTN_SMEM>>>();

    dim3 go(En / 128, Mn / 128);
    gemm_wo_kernel<<<go, 256, GEMM_SMEM>>>(out);
}

// round 7
// speedup vs baseline: 8.1706x; 1.2453x over previous
#include <cuda_runtime.h>
#include <cuda_bf16.h>
#include <cuda_fp16.h>
#include <cstdint>
#include <math.h>

#define Bn  4
#define Sn  2048
#define En  1024
#define Hn  16
#define DKn 64
#define Mn  (Bn * Sn)   // 8192

// ==================== device global scratch ====================
__device__ __half g_Xf[Mn * En];                  // x fp16
__device__ __half g_Wf[4 * En * En];              // Wq,Wk,Wv,Wo fp16
__device__ __half g_Qf[Mn * En];                  // (B,H,S,DK) pre-scaled by 1/8
__device__ __half g_Kf[Mn * En];                  // (B,H,S,DK)
__device__ __half g_Vf[Mn * En];                  // (B,H,DK,S) d-major
__device__ __half g_Cf[Mn * En];                  // ctx (B,S,E) fp16

// ==================== helpers ====================
__device__ __forceinline__ uint32_t smem_to_u32(const void* p) {
    uint32_t a;
    asm("{ .reg .u64 t; cvta.to.shared.u64 t, %1; cvt.u32.u64 %0, t; }"
        : "=r"(a) : "l"(p));
    return a;
}
__device__ __forceinline__ void ldsm4(uint32_t addr, uint32_t r[4]) {
    asm volatile("ldmatrix.sync.aligned.m8n8.x4.shared.b16 {%0,%1,%2,%3}, [%4];"
                 : "=r"(r[0]), "=r"(r[1]), "=r"(r[2]), "=r"(r[3]) : "r"(addr));
}
__device__ __forceinline__ void mma16816h(float d[4], const uint32_t a[4],
                                          uint32_t b0, uint32_t b1) {
    asm volatile(
        "mma.sync.aligned.m16n8k16.row.col.f32.f16.f16.f32 "
        "{%0,%1,%2,%3}, {%4,%5,%6,%7}, {%8,%9}, {%0,%1,%2,%3};"
        : "+f"(d[0]), "+f"(d[1]), "+f"(d[2]), "+f"(d[3])
        : "r"(a[0]), "r"(a[1]), "r"(a[2]), "r"(a[3]), "r"(b0), "r"(b1));
}
#define CP16(saddr, gptr) \
    asm volatile("cp.async.cg.shared.global [%0], [%1], 16;" \
                 :: "r"(saddr), "l"(gptr))
#define CP_COMMIT() asm volatile("cp.async.commit_group;")
#define CP_WAIT0()  asm volatile("cp.async.wait_group 0;")
#define CP_WAIT1()  asm volatile("cp.async.wait_group 1;")

__device__ __forceinline__ uint32_t pack_f16x2(float a, float b) {
    uint32_t r;
    asm("cvt.rn.f16x2.f32 %0, %1, %2;" : "=r"(r) : "f"(b), "f"(a));
    return r;
}

// ==================== convert inputs to fp16 (1 launch) ====================
#define NX4 (Mn * En / 4)   // 2097152
#define NW4 (En * En / 4)   // 262144 = 2^18
__global__ __launch_bounds__(256)
void split_all_kernel(const float* __restrict__ x,
                      const float* __restrict__ wq, const float* __restrict__ wk,
                      const float* __restrict__ wv, const float* __restrict__ wo)
{
    int i = blockIdx.x * blockDim.x + threadIdx.x;
    const float* src; __half* dst; int off;
    if (i < NX4) { src = x; dst = g_Xf; off = i; }
    else {
        int j = i - NX4;
        int s = j >> 18;
        off = j & (NW4 - 1);
        src = (s == 0) ? wq : (s == 1) ? wk : (s == 2) ? wv : wo;
        dst = g_Wf + (size_t)s * En * En;
    }
    float4 v = ((const float4*)src)[off];
    ((__half2*)dst)[off * 2 + 0] =
        __halves2half2(__float2half_rn(v.x), __float2half_rn(v.y));
    ((__half2*)dst)[off * 2 + 1] =
        __halves2half2(__float2half_rn(v.z), __float2half_rn(v.w));
}

// ==================== unified fp16 GEMM: Y = A @ W^T ====================
// 128x128 tile, 8 warps (wm2 x wn4), warp 64x32, BK=64, double buffer.
// mode 0: z=0/1/2 -> Q(scaled)/K s-major, V d-major. mode 1: Wo -> fp32 out.
#define QGSB 144                 // 64 fp16 = 128B + 16 pad
#define QGT  (128 * QGSB)        // 18432
#define QKV_SMEM (4 * QGT)       // 73728

#define QKV_ISSUE(buf, k0) do {                                             \
    _Pragma("unroll")                                                       \
    for (int _t = 0; _t < 2; _t++) {                                        \
        const __half* _src = (_t == 0) ? pA : pB;                           \
        uint32_t _db = sb + ((buf) * 2 + _t) * QGT;                         \
        _Pragma("unroll")                                                   \
        for (int _i = 0; _i < 4; _i++) {                                    \
            int _u = _i * 256 + tid; int _r = _u >> 3; int _c = _u & 7;     \
            CP16(_db + _r * QGSB + _c * 16,                                 \
                 _src + (size_t)_r * En + (k0) + _c * 8);                   \
        }                                                                   \
    }                                                                       \
    CP_COMMIT();                                                            \
} while (0)

__global__ __launch_bounds__(256, 2)
void gemm_f16(int mode, float* __restrict__ outp)
{
    extern __shared__ char sm[];
    const uint32_t sb = smem_to_u32(sm);
    const int tid = threadIdx.x, wid = tid >> 5, lane = tid & 31;
    const int wm = wid >> 2, wn = wid & 3;
    const int z = blockIdx.z;
    const int ws = (mode == 1) ? 3 : z;
    const int rowBase = blockIdx.y * 128, colBase = blockIdx.x * 128;

    const __half* __restrict__ pA =
        (mode == 0 ? g_Xf : g_Cf) + (size_t)rowBase * En;
    const __half* __restrict__ pB =
        g_Wf + (size_t)ws * En * En + (size_t)colBase * En;

    float acc[4][4][4];
#pragma unroll
    for (int a = 0; a < 4; a++)
#pragma unroll
        for (int b = 0; b < 4; b++)
#pragma unroll
            for (int c = 0; c < 4; c++) acc[a][b][c] = 0.f;

    const int rin = lane & 15;
    const int chf = lane >> 4;

    QKV_ISSUE(0, 0);
#pragma unroll 1
    for (int ch = 0; ch < 16; ch++) {
        const int buf = ch & 1;
        if (ch < 15) { QKV_ISSUE(buf ^ 1, (ch + 1) * 64); CP_WAIT1(); }
        else         { CP_WAIT0(); }
        __syncthreads();
        const uint32_t aB = sb + (buf * 2 + 0) * QGT;
        const uint32_t bB = sb + (buf * 2 + 1) * QGT;

#pragma unroll
        for (int ks = 0; ks < 4; ks++) {
            uint32_t kf[2][4];
#pragma unroll
            for (int p = 0; p < 2; p++) {
                uint32_t off = (uint32_t)((wn * 32 + p * 16 + rin) * QGSB
                                          + (ks * 16 + chf * 8) * 2);
                ldsm4(bB + off, kf[p]);
            }
#pragma unroll
            for (int mt = 0; mt < 4; mt++) {
                uint32_t af[4];
                uint32_t off = (uint32_t)((wm * 64 + mt * 16 + rin) * QGSB
                                          + (ks * 16 + chf * 8) * 2);
                ldsm4(aB + off, af);
#pragma unroll
                for (int nt = 0; nt < 4; nt++) {
                    const int p = nt >> 1, e = nt & 1;
                    mma16816h(acc[mt][nt], af, kf[p][e], kf[p][2 + e]);
                }
            }
        }
        __syncthreads();
    }

    const int qr = lane >> 2, qc = (lane & 3) * 2;
    const float oscale = (mode == 0 && z == 0) ? 0.125f : 1.0f;
#pragma unroll
    for (int mt = 0; mt < 4; mt++)
#pragma unroll
        for (int hf = 0; hf < 2; hf++) {
            const int m = rowBase + wm * 64 + mt * 16 + qr + hf * 8;
#pragma unroll
            for (int nt = 0; nt < 4; nt++) {
                const int n = colBase + wn * 32 + nt * 8 + qc;
                const float v0 = acc[mt][nt][hf * 2 + 0] * oscale;
                const float v1 = acc[mt][nt][hf * 2 + 1] * oscale;
                if (mode == 1) {
                    float2 o; o.x = v0; o.y = v1;
                    *(float2*)&outp[(size_t)m * En + n] = o;
                } else {
                    const int b = m >> 11, s = m & (Sn - 1);
                    const int h = n >> 6, d = n & 63;
                    __half h0 = __float2half_rn(v0);
                    __half h1 = __float2half_rn(v1);
                    if (z == 2) {
                        size_t i0 = ((size_t)(b * Hn + h) * DKn + d) * Sn + s;
                        g_Vf[i0] = h0; g_Vf[i0 + Sn] = h1;
                    } else {
                        size_t i0 = ((size_t)(b * Hn + h) * Sn + s) * DKn + d;
                        __half* dst = (z == 0) ? g_Qf : g_Kf;
                        *(__half2*)&dst[i0] = __halves2half2(h0, h1);
                    }
                }
            }
        }
}

// ==================== MMA flash attention (fp16, 2 syncs/tile) ============
#define QKSB 144
#define VSB  272
#define KBUF 18432
#define VBUF 17408
#define oQ 0
#define oK 18432
#define oV 55296
#define oRed 90112                  // redm 1024 + redl 1024
#define oStage 92160                // 128*64*4
#define ATTN_SMEM 124928

#define ISSUE_KV(buf, kv) do {                                              \
    uint32_t _kb = sb + oK + (buf) * KBUF;                                  \
    uint32_t _vb = sb + oV + (buf) * VBUF;                                  \
    _Pragma("unroll")                                                       \
    for (int _i = 0; _i < 4; _i++) {                                        \
        int _u = _i * 256 + tid; int _r = _u >> 3; int _c = _u & 7;         \
        CP16(_kb + _r * QKSB + _c * 16,                                     \
             g_Kf + base + (size_t)((kv) + _r) * DKn + _c * 8);             \
    }                                                                       \
    _Pragma("unroll")                                                       \
    for (int _i = 0; _i < 4; _i++) {                                        \
        int _u = _i * 256 + tid; int _r = _u >> 4; int _c = _u & 15;        \
        CP16(_vb + _r * VSB + _c * 16,                                      \
             g_Vf + base + (size_t)_r * Sn + (kv) + _c * 8);                \
    }                                                                       \
    CP_COMMIT();                                                            \
} while (0)

__global__ __launch_bounds__(256, 1)
void attn_mma_kernel()
{
    extern __shared__ char sm[];
    const uint32_t sb = smem_to_u32(sm);
    float* redm = (float*)(sm + oRed);
    float* redl = (float*)(sm + oRed + 1024);
    float* stage = (float*)(sm + oStage);

    const int tid = threadIdx.x, wid = tid >> 5, lane = tid & 31;
    const int wm = wid >> 1, wn = wid & 1;
    const int q0 = blockIdx.x * 128;
    const int bh = blockIdx.y;
    const size_t base = (size_t)bh * Sn * DKn;

    const int rin = lane & 15;
    const int chf = lane >> 4;
    const int qr = lane >> 2, qc = (lane & 3) * 2;

#pragma unroll
    for (int i = 0; i < 4; i++) {
        int u = i * 256 + tid; int r = u >> 3; int c = u & 7;
        CP16(sb + oQ + r * QKSB + c * 16,
             g_Qf + base + (size_t)(q0 + r) * DKn + c * 8);
    }
    CP_COMMIT();

    ISSUE_KV(0, 0);

    float acc_o[2][8][4];
    float m_st[2][2], l_st[2][2];
#pragma unroll
    for (int a = 0; a < 2; a++)
#pragma unroll
        for (int b = 0; b < 8; b++)
#pragma unroll
            for (int c = 0; c < 4; c++) acc_o[a][b][c] = 0.f;
#pragma unroll
    for (int a = 0; a < 2; a++)
#pragma unroll
        for (int b = 0; b < 2; b++) { m_st[a][b] = -1e30f; l_st[a][b] = 0.f; }

#pragma unroll 1
    for (int it = 0; it < 16; it++) {
        const int buf = it & 1;
        if (it < 15) { ISSUE_KV(buf ^ 1, (it + 1) * 128); CP_WAIT1(); }
        else         { CP_WAIT0(); }
        __syncthreads();   // KV tile ready; also protects red arrays (WAR)
        const uint32_t kB = sb + oK + buf * KBUF;
        const uint32_t vB = sb + oV + buf * VBUF;

        // ---- S = Q K^T (Q pre-scaled by 1/8) ----
        float s[2][8][4];
#pragma unroll
        for (int a = 0; a < 2; a++)
#pragma unroll
            for (int b = 0; b < 8; b++)
#pragma unroll
                for (int c = 0; c < 4; c++) s[a][b][c] = 0.f;

#pragma unroll
        for (int ks = 0; ks < 4; ks++) {
            uint32_t qf[2][4];
#pragma unroll
            for (int mt = 0; mt < 2; mt++) {
                uint32_t off = (uint32_t)((wm * 32 + mt * 16 + rin) * QKSB
                                          + (ks * 16 + chf * 8) * 2);
                ldsm4(sb + oQ + off, qf[mt]);
            }
            uint32_t kf[4][4];
#pragma unroll
            for (int p = 0; p < 4; p++) {
                uint32_t off = (uint32_t)((wn * 64 + p * 16 + rin) * QKSB
                                          + (ks * 16 + chf * 8) * 2);
                ldsm4(kB + off, kf[p]);
            }
#pragma unroll
            for (int mt = 0; mt < 2; mt++)
#pragma unroll
                for (int nt = 0; nt < 8; nt++) {
                    const int p = nt >> 1, e = nt & 1;
                    mma16816h(s[mt][nt], qf[mt], kf[p][e], kf[p][2 + e]);
                }
        }

        // ---- warp-local max AND exp-sum, one exchange ----
        float m_loc[2][2];
#pragma unroll
        for (int mt = 0; mt < 2; mt++)
#pragma unroll
            for (int hf = 0; hf < 2; hf++) {
                float mx = -1e30f;
#pragma unroll
                for (int nt = 0; nt < 8; nt++)
#pragma unroll
                    for (int e2 = 0; e2 < 2; e2++)
                        mx = fmaxf(mx, s[mt][nt][hf * 2 + e2]);
                mx = fmaxf(mx, __shfl_xor_sync(0xffffffffu, mx, 1));
                mx = fmaxf(mx, __shfl_xor_sync(0xffffffffu, mx, 2));
                m_loc[mt][hf] = mx;
                float sum = 0.f;
#pragma unroll
                for (int nt = 0; nt < 8; nt++)
#pragma unroll
                    for (int e2 = 0; e2 < 2; e2++) {
                        float p = __expf(s[mt][nt][hf * 2 + e2] - mx);
                        s[mt][nt][hf * 2 + e2] = p;
                        sum += p;
                    }
                sum += __shfl_xor_sync(0xffffffffu, sum, 1);
                sum += __shfl_xor_sync(0xffffffffu, sum, 2);
                if ((lane & 3) == 0) {
                    const int row = wm * 32 + mt * 16 + qr + hf * 8;
                    redm[row * 2 + wn] = mx;
                    redl[row * 2 + wn] = sum;
                }
            }
        __syncthreads();

        // ---- global update + P rescale factors ----
        float fact[2][2];
#pragma unroll
        for (int mt = 0; mt < 2; mt++)
#pragma unroll
            for (int hf = 0; hf < 2; hf++) {
                const int row = wm * 32 + mt * 16 + qr + hf * 8;
                const float m0 = redm[row * 2], m1 = redm[row * 2 + 1];
                const float mnew = fmaxf(m_st[mt][hf], fmaxf(m0, m1));
                const float alpha = __expf(m_st[mt][hf] - mnew);
                m_st[mt][hf] = mnew;
                l_st[mt][hf] = l_st[mt][hf] * alpha
                             + redl[row * 2] * __expf(m0 - mnew)
                             + redl[row * 2 + 1] * __expf(m1 - mnew);
                fact[mt][hf] = __expf(m_loc[mt][hf] - mnew);
#pragma unroll
                for (int nt = 0; nt < 8; nt++) {
                    acc_o[mt][nt][hf * 2 + 0] *= alpha;
                    acc_o[mt][nt][hf * 2 + 1] *= alpha;
                }
            }

        // ---- O += P @ V (P scaled by fact at pack time) ----
#pragma unroll
        for (int kc = 0; kc < 4; kc++) {
            uint32_t pa[2][4];
#pragma unroll
            for (int mt = 0; mt < 2; mt++) {
                const float* s0 = s[mt][2 * kc];
                const float* s1 = s[mt][2 * kc + 1];
                const float f0 = fact[mt][0], f1 = fact[mt][1];
                pa[mt][0] = pack_f16x2(s0[0] * f0, s0[1] * f0);
                pa[mt][1] = pack_f16x2(s0[2] * f1, s0[3] * f1);
                pa[mt][2] = pack_f16x2(s1[0] * f0, s1[1] * f0);
                pa[mt][3] = pack_f16x2(s1[2] * f1, s1[3] * f1);
            }
            uint32_t vf[4][4];
#pragma unroll
            for (int p = 0; p < 4; p++) {
                uint32_t off = (uint32_t)((p * 16 + rin) * VSB
                                          + (wn * 64 + kc * 16 + chf * 8) * 2);
                ldsm4(vB + off, vf[p]);
            }
#pragma unroll
            for (int mt = 0; mt < 2; mt++)
#pragma unroll
                for (int nt = 0; nt < 8; nt++) {
                    const int p = nt >> 1, e = nt & 1;
                    mma16816h(acc_o[mt][nt], pa[mt], vf[p][e], vf[p][2 + e]);
                }
        }
    }

    // ---- cross-warp (wn) merge + write ctx fp16 ----
    if (wn == 0) {
#pragma unroll
        for (int mt = 0; mt < 2; mt++)
#pragma unroll
            for (int hf = 0; hf < 2; hf++) {
                const int q = wm * 32 + mt * 16 + qr + hf * 8;
#pragma unroll
                for (int nt = 0; nt < 8; nt++) {
                    float2 v;
                    v.x = acc_o[mt][nt][hf * 2 + 0];
                    v.y = acc_o[mt][nt][hf * 2 + 1];
                    *(float2*)&stage[q * 64 + nt * 8 + qc] = v;
                }
            }
    }
    __syncthreads();
    if (wn == 1) {
        const int b = bh >> 4, h = bh & 15;
#pragma unroll
        for (int mt = 0; mt < 2; mt++)
#pragma unroll
            for (int hf = 0; hf < 2; hf++) {
                const int q = wm * 32 + mt * 16 + qr + hf * 8;
                const float rinv = 1.f / l_st[mt][hf];
#pragma unroll
                for (int nt = 0; nt < 8; nt++) {
                    float2 prev = *(const float2*)&stage[q * 64 + nt * 8 + qc];
                    float v0 = (prev.x + acc_o[mt][nt][hf * 2 + 0]) * rinv;
                    float v1 = (prev.y + acc_o[mt][nt][hf * 2 + 1]) * rinv;
                    size_t idx = ((size_t)b * Sn + q0 + q) * En + h * DKn + nt * 8 + qc;
                    *(__half2*)&g_Cf[idx] =
                        __halves2half2(__float2half_rn(v0), __float2half_rn(v1));
                }
            }
    }
}

// ==================== launch ====================
extern "C" void kernel_launch(void* const* d_in, const int* in_sizes, int n_in,
                              void* d_out, int out_size)
{
    (void)in_sizes; (void)n_in; (void)out_size;
    const float* x  = (const float*)d_in[0];
    const float* Wq = (const float*)d_in[1];
    const float* Wk = (const float*)d_in[2];
    const float* Wv = (const float*)d_in[3];
    const float* Wo = (const float*)d_in[4];
    float* out = (float*)d_out;

    cudaFuncSetAttribute(gemm_f16,
                         cudaFuncAttributeMaxDynamicSharedMemorySize, QKV_SMEM);
    cudaFuncSetAttribute(attn_mma_kernel,
                         cudaFuncAttributeMaxDynamicSharedMemorySize, ATTN_SMEM);

    split_all_kernel<<<(NX4 + 4 * NW4) / 256, 256>>>(x, Wq, Wk, Wv, Wo);

    dim3 gq(En / 128, Mn / 128, 3);
    gemm_f16<<<gq, 256, QKV_SMEM>>>(0, nullptr);

    dim3 ga(Sn / 128, Bn * Hn);
    attn_mma_kernel<<<ga, 256, ATTN_SMEM>>>();

    dim3 go(En / 128, Mn / 128);
    gemm_f16<<<go, 256, QKV_SMEM>>>(1, out);
}